// round 12
// baseline (speedup 1.0000x reference)
#include <cuda_runtime.h>
#include <cuda_fp16.h>
#include <cstdint>
#include <math.h>

// ---------------------------------------------------------------------------
// MultiHeadAttention: B=8, S=1024, D=1024, H=16, HD=64
// Round 11: GEMM -> true 4-stage cp.async pipeline (BK=32, stride 48,
// one barrier per iteration, staging issued BEFORE compute). 2 CTAs/SM.
// Attention and prep unchanged.
// ---------------------------------------------------------------------------

#define B_  8
#define S_  1024
#define D_  1024
#define H_  16
#define HD_ 64
#define M_TOTAL (B_ * S_)          // 8192

__device__ __half g_xh[(size_t)M_TOTAL * D_];
__device__ __half g_qh[(size_t)M_TOTAL * D_];
__device__ __half g_kh[(size_t)M_TOTAL * D_];
__device__ __half g_vt[(size_t)B_ * H_ * HD_ * S_];   // [B][H][d][key-perm]
__device__ __half g_ch[(size_t)M_TOTAL * D_];
__device__ __half g_wq[(size_t)D_ * D_];
__device__ __half g_wk[(size_t)D_ * D_];
__device__ __half g_wv[(size_t)D_ * D_];
__device__ __half g_wo[(size_t)D_ * D_];

// ---------------------------------------------------------------------------
// helpers
// ---------------------------------------------------------------------------
__device__ __forceinline__ uint32_t smem_u32(const void* p) {
    uint32_t a;
    asm("{ .reg .u64 t; cvta.to.shared.u64 t, %1; cvt.u32.u64 %0, t; }"
        : "=r"(a) : "l"(p));
    return a;
}

__device__ __forceinline__ void cpa16(uint32_t dst, const void* src) {
    asm volatile("cp.async.cg.shared.global [%0], [%1], 16;"
                 :: "r"(dst), "l"(src) : "memory");
}
__device__ __forceinline__ void cpa_commit() {
    asm volatile("cp.async.commit_group;" ::: "memory");
}
__device__ __forceinline__ void cpa_wait2() {
    asm volatile("cp.async.wait_group 2;" ::: "memory");
}
__device__ __forceinline__ void cpa_wait1() {
    asm volatile("cp.async.wait_group 1;" ::: "memory");
}
__device__ __forceinline__ void cpa_wait0() {
    asm volatile("cp.async.wait_group 0;" ::: "memory");
}

__device__ __forceinline__ void mma_f16(float* c,
                                        uint32_t a0, uint32_t a1, uint32_t a2, uint32_t a3,
                                        uint32_t b0, uint32_t b1) {
    asm volatile(
        "mma.sync.aligned.m16n8k16.row.col.f32.f16.f16.f32 "
        "{%0,%1,%2,%3}, {%4,%5,%6,%7}, {%8,%9}, {%0,%1,%2,%3};\n"
        : "+f"(c[0]), "+f"(c[1]), "+f"(c[2]), "+f"(c[3])
        : "r"(a0), "r"(a1), "r"(a2), "r"(a3), "r"(b0), "r"(b1));
}

__device__ __forceinline__ uint32_t pack2(float lo, float hi) {
    __half2 h = __floats2half2_rn(lo, hi);
    return *reinterpret_cast<uint32_t*>(&h);
}

// ---------------------------------------------------------------------------
// Fused pre-pass (unchanged)
// ---------------------------------------------------------------------------
#define N4X (M_TOTAL * D_ / 4)     // 2097152
#define N4W (D_ * D_ / 4)          // 262144

__global__ __launch_bounds__(256)
void prep_all(const float* __restrict__ x,
              const float* __restrict__ Wq, const float* __restrict__ Wk,
              const float* __restrict__ Wv, const float* __restrict__ Wo)
{
    const int i = blockIdx.x * blockDim.x + threadIdx.x;
    const float* src;
    __half* dst;
    int j;
    if (i < N4X)                  { src = x;  dst = g_xh; j = i; }
    else {
        const int r = i - N4X;
        const int w = r >> 18;
        j = r & (N4W - 1);
        if      (w == 0) { src = Wq; dst = g_wq; }
        else if (w == 1) { src = Wk; dst = g_wk; }
        else if (w == 2) { src = Wv; dst = g_wv; }
        else             { src = Wo; dst = g_wo; }
    }
    const float4 v = ((const float4*)src)[j];
    const int flat = j << 2;
    const int base = flat & ~15;
    const int u0   = (flat & 15) >> 1;
    const int p0   = ((u0 & 3) << 1) | (u0 >> 2);
    const int u1   = u0 + 1;
    const int p1   = ((u1 & 3) << 1) | (u1 >> 2);
    *(__half2*)(dst + base + 2 * p0) = __floats2half2_rn(v.x, v.y);
    *(__half2*)(dst + base + 2 * p1) = __floats2half2_rn(v.z, v.w);
}

// ---------------------------------------------------------------------------
// fp16 GEMM (NT): CTA 128x128, 128 threads (4 warps of 64x64), BK=32,
// 4-stage cp.async pipeline, ONE barrier per iteration, staging before
// compute. Stride 48 halves (24 words): frag LDS.64 banks 24g+8ks+2tig,
// conflict-free per 16-lane phase. 2 CTAs/SM (96KB smem).
// ---------------------------------------------------------------------------
#define GBM 128
#define GBN 128
#define GBKH 32
#define GLDH 48
#define GBUFH ((GBM + GBN) * GLDH)               // 12288 halves / stage
#define GEMM_SMEM (4 * GBUFH * 2)                // 98304 bytes

__global__ __launch_bounds__(128, 2)
void gemm_h(const __half* __restrict__ A,
            const __half* __restrict__ W0, const __half* __restrict__ W1,
            const __half* __restrict__ W2,
            const float* __restrict__ bb0, const float* __restrict__ bb1,
            const float* __restrict__ bb2,
            void* C0, void* C1, void* C2,
            int oproj)
{
    extern __shared__ __half smh[];
    const int z = blockIdx.z;
    const __half* Bw   = (z == 0) ? W0  : (z == 1) ? W1  : W2;
    const float*  bias = (z == 0) ? bb0 : (z == 1) ? bb1 : bb2;
    void*         C    = (z == 0) ? C0  : (z == 1) ? C1  : C2;
    const float scale  = (!oproj && z == 0) ? 0.125f : 1.0f;

    const int tid  = threadIdx.x;
    const int wid  = tid >> 5;
    const int lane = tid & 31;
    const int g    = lane >> 2;
    const int tig  = lane & 3;
    const int wm   = (wid & 1) * 64;
    const int wn   = (wid >> 1) * 64;
    const int bm   = blockIdx.y * GBM;
    const int bn   = blockIdx.x * GBN;

    const __half* Abase = A  + (size_t)bm * D_;
    const __half* Bbase = Bw + (size_t)bn * D_;
    const uint32_t su   = smem_u32(smh);

    // stage one BK=32 slab (A: 128x32, B: 128x32); 4 chunks/row, 128 threads
#define G_ISSUE(slab) do {                                                 \
        const uint32_t s0 = su + (uint32_t)((slab) & 3) * (GBUFH * 2);     \
        const int k0 = (slab) * GBKH;                                      \
        _Pragma("unroll")                                                  \
        for (int j = 0; j < 4; j++) {                                      \
            const int i = tid + 128 * j;      /* A: 512 16B chunks */      \
            const int row = i >> 2, ch = (i & 3) * 8;                      \
            cpa16(s0 + (row * GLDH + ch) * 2,                              \
                  Abase + (size_t)row * D_ + k0 + ch);                     \
        }                                                                  \
        _Pragma("unroll")                                                  \
        for (int j = 0; j < 4; j++) {                                      \
            const int i = tid + 128 * j;      /* B: 512 16B chunks */      \
            const int row = i >> 2, ch = (i & 3) * 8;                      \
            cpa16(s0 + ((GBM + row) * GLDH + ch) * 2,                      \
                  Bbase + (size_t)row * D_ + k0 + ch);                     \
        }                                                                  \
        cpa_commit();                                                      \
    } while (0)

    float acc[4][8][4];
#pragma unroll
    for (int mt = 0; mt < 4; mt++)
#pragma unroll
        for (int nt = 0; nt < 8; nt++)
#pragma unroll
            for (int i = 0; i < 4; i++) acc[mt][nt][i] = 0.f;

    const int NT = D_ / GBKH;   // 32
    G_ISSUE(0);
    G_ISSUE(1);
    G_ISSUE(2);

    for (int t = 0; t < NT; t++) {
        // slab t complete when pending groups <= (slabs issued) - (t+1)
        if (t <= NT - 3)      cpa_wait2();
        else if (t == NT - 2) cpa_wait1();
        else                  cpa_wait0();
        __syncthreads();      // single barrier: publishes slab t, fences
                              // upcoming writes to buffer (t+3)&3 from
                              // last iteration's readers of that buffer

        if (t + 3 < NT) G_ISSUE(t + 3);   // staging BEFORE compute

        const __half* as = smh + (t & 3) * GBUFH;
        const __half* bs = as + GBM * GLDH;
#pragma unroll
        for (int ks = 0; ks < 2; ks++) {
            uint2 alo[4], ahi[4];
#pragma unroll
            for (int mt = 0; mt < 4; mt++) {
                const int r0 = (wm + mt * 16 + g) * GLDH + ks * 16 + 4 * tig;
                alo[mt] = *(const uint2*)&as[r0];
                ahi[mt] = *(const uint2*)&as[r0 + 8 * GLDH];
            }
#pragma unroll
            for (int nt = 0; nt < 8; nt++) {
                const uint2 bb = *(const uint2*)&bs[(wn + nt * 8 + g) * GLDH
                                                    + ks * 16 + 4 * tig];
#pragma unroll
                for (int mt = 0; mt < 4; mt++)
                    mma_f16(acc[mt][nt], alo[mt].x, ahi[mt].x, alo[mt].y, ahi[mt].y,
                            bb.x, bb.y);
            }
        }
    }
#undef G_ISSUE

    if (oproj) {
        float* Co = (float*)C;
#pragma unroll
        for (int mt = 0; mt < 4; mt++) {
            const int row0 = bm + wm + mt * 16 + g;
#pragma unroll
            for (int nt = 0; nt < 8; nt++) {
                const int col = bn + wn + nt * 8 + 2 * tig;
                const float c0 = bias[col], c1 = bias[col + 1];
                float2 v0 = make_float2(acc[mt][nt][0] + c0, acc[mt][nt][1] + c1);
                float2 v1 = make_float2(acc[mt][nt][2] + c0, acc[mt][nt][3] + c1);
                *(float2*)(Co + (size_t)row0 * D_ + col)       = v0;
                *(float2*)(Co + (size_t)(row0 + 8) * D_ + col) = v1;
            }
        }
    } else if (z < 2) {
        __half* Ch = (__half*)C;
#pragma unroll
        for (int mt = 0; mt < 4; mt++) {
            const int row0 = bm + wm + mt * 16 + g;
#pragma unroll
            for (int nt = 0; nt < 8; nt++) {
                const int n = bn + wn + nt * 8 + 2 * tig;
                const int dsti = bn + wn + (nt & ~1) * 8 + 4 * tig + 2 * (nt & 1);
                const float c0 = bias[n], c1 = bias[n + 1];
                *(__half2*)(Ch + (size_t)row0 * D_ + dsti) =
                    __floats2half2_rn((acc[mt][nt][0] + c0) * scale,
                                      (acc[mt][nt][1] + c1) * scale);
                *(__half2*)(Ch + (size_t)(row0 + 8) * D_ + dsti) =
                    __floats2half2_rn((acc[mt][nt][2] + c0) * scale,
                                      (acc[mt][nt][3] + c1) * scale);
            }
        }
    } else {
        // transposed Vt output with unit-permuted key positions
        __half* Vt = (__half*)C;
#pragma unroll
        for (int mt = 0; mt < 4; mt++) {
            const int row0 = bm + wm + mt * 16 + g;
#pragma unroll
            for (int nt = 0; nt < 8; nt++) {
                const int n  = bn + wn + nt * 8 + 2 * tig;
                const float c0 = bias[n], c1 = bias[n + 1];
#pragma unroll
                for (int e = 0; e < 4; e++) {
                    const int row = row0 + (e >> 1) * 8;
                    const int col = n + (e & 1);
                    const float val = acc[mt][nt][e] + ((e & 1) ? c1 : c0);
                    const int bIdx = row >> 10, s = row & 1023;
                    const int u    = (s >> 1) & 7;
                    const int sp   = (s & ~15) + 2 * (((u & 3) << 1) | (u >> 2)) + (s & 1);
                    const int head = col >> 6,  dd = col & 63;
                    Vt[(((size_t)(bIdx * H_ + head)) * HD_ + dd) * S_ + sp] =
                        __float2half_rn(val);
                }
            }
        }
    }
}

// ---------------------------------------------------------------------------
// Flash attention (unchanged): fp16 m16n8k16, cp.async double-buffered K/Vt,
// 2 CTAs/SM, Q frags hoisted, Vt key-permuted LDS.64 B-frags.
// ---------------------------------------------------------------------------
#define QLDH 80
#define KLDH 80
#define VLDH 80
#define OFF_K(buf) (128 * QLDH + (buf) * 64 * KLDH)
#define OFF_V(buf) (128 * QLDH + 2 * 64 * KLDH + (buf) * 64 * VLDH)
#define ATTN_SMEM ((128 * QLDH + 2 * 64 * KLDH + 2 * 64 * VLDH) * 2)  // 61440 B

__global__ __launch_bounds__(128, 2)
void attn_h(const __half* __restrict__ Q, const __half* __restrict__ K,
            const __half* __restrict__ Vt, __half* __restrict__ O)
{
    extern __shared__ __half smh[];
    const uint32_t su = smem_u32(smh);

    const int q0   = blockIdx.x * 128;
    const int h    = blockIdx.y;
    const int b    = blockIdx.z;
    const int tid  = threadIdx.x;
    const int w    = tid >> 5;
    const int lane = tid & 31;
    const int g    = lane >> 2;
    const int tig  = lane & 3;

    const size_t base  = (size_t)b * S_ * D_ + (size_t)h * HD_;
    const size_t vbase = ((size_t)(b * H_ + h)) * HD_ * S_;

#define A_ISSUE(t, buf) do {                                               \
        const __half* Kb = K  + base + (size_t)((t) * 64) * D_;            \
        const __half* Vb = Vt + vbase + (t) * 64;                          \
        _Pragma("unroll")                                                  \
        for (int j = 0; j < 4; j++) {                                      \
            const int i = tid + 128 * j;                                   \
            const int row = i >> 3, ch = (i & 7) * 8;                      \
            cpa16(su + (OFF_K(buf) + row * KLDH + ch) * 2,                 \
                  Kb + (size_t)row * D_ + ch);                             \
            cpa16(su + (OFF_V(buf) + row * VLDH + ch) * 2,                 \
                  Vb + (size_t)row * S_ + ch);                             \
        }                                                                  \
        cpa_commit();                                                      \
    } while (0)

    {
        const __half* Qb = Q + base + (size_t)q0 * D_;
#pragma unroll
        for (int j = 0; j < 8; j++) {
            const int i = tid + 128 * j;
            const int row = i >> 3, ch = (i & 7) * 8;
            cpa16(su + (row * QLDH + ch) * 2, Qb + (size_t)row * D_ + ch);
        }
        const __half* Kb = K + base;
        const __half* Vb = Vt + vbase;
#pragma unroll
        for (int j = 0; j < 4; j++) {
            const int i = tid + 128 * j;
            const int row = i >> 3, ch = (i & 7) * 8;
            cpa16(su + (OFF_K(0) + row * KLDH + ch) * 2, Kb + (size_t)row * D_ + ch);
            cpa16(su + (OFF_V(0) + row * VLDH + ch) * 2, Vb + (size_t)row * S_ + ch);
        }
        cpa_commit();
        A_ISSUE(1, 1);
    }

    float mrow[2][2], lrow[2][2];
#pragma unroll
    for (int mt = 0; mt < 2; mt++) {
        mrow[mt][0] = -1e30f; mrow[mt][1] = -1e30f;
        lrow[mt][0] = 0.f;    lrow[mt][1] = 0.f;
    }
    float o[2][8][4];
#pragma unroll
    for (int mt = 0; mt < 2; mt++)
#pragma unroll
        for (int nt = 0; nt < 8; nt++)
#pragma unroll
            for (int i = 0; i < 4; i++) o[mt][nt][i] = 0.f;

    uint2 qlo[2][4], qhi[2][4];

    const int NTILE = S_ / 64;   // 16
    for (int t = 0; t < NTILE; t++) {
        if (t == NTILE - 1) cpa_wait0(); else cpa_wait1();
        __syncthreads();

        if (t == 0) {
#pragma unroll
            for (int ks = 0; ks < 4; ks++)
#pragma unroll
                for (int mt = 0; mt < 2; mt++) {
                    const int r0 = (w * 32 + mt * 16 + g) * QLDH + ks * 16 + 4 * tig;
                    qlo[mt][ks] = *(const uint2*)&smh[r0];
                    qhi[mt][ks] = *(const uint2*)&smh[r0 + 8 * QLDH];
                }
        }

        const __half* sK = smh + OFF_K(t & 1);
        const __half* sV = smh + OFF_V(t & 1);

        float s[2][8][4];
#pragma unroll
        for (int mt = 0; mt < 2; mt++)
#pragma unroll
            for (int nt = 0; nt < 8; nt++)
#pragma unroll
                for (int i = 0; i < 4; i++) s[mt][nt][i] = 0.f;

#pragma unroll
        for (int ks = 0; ks < 4; ks++) {
#pragma unroll
            for (int nt = 0; nt < 8; nt++) {
                const uint2 bb = *(const uint2*)&sK[(nt * 8 + g) * KLDH
                                                    + ks * 16 + 4 * tig];
                mma_f16(s[0][nt], qlo[0][ks].x, qhi[0][ks].x, qlo[0][ks].y,
                        qhi[0][ks].y, bb.x, bb.y);
                mma_f16(s[1][nt], qlo[1][ks].x, qhi[1][ks].x, qlo[1][ks].y,
                        qhi[1][ks].y, bb.x, bb.y);
            }
        }

#pragma unroll
        for (int mt = 0; mt < 2; mt++) {
            float mx0 = -1e30f, mx1 = -1e30f;
#pragma unroll
            for (int nt = 0; nt < 8; nt++) {
                mx0 = fmaxf(mx0, fmaxf(s[mt][nt][0], s[mt][nt][1]));
                mx1 = fmaxf(mx1, fmaxf(s[mt][nt][2], s[mt][nt][3]));
            }
            mx0 = fmaxf(mx0, __shfl_xor_sync(0xffffffffu, mx0, 1));
            mx0 = fmaxf(mx0, __shfl_xor_sync(0xffffffffu, mx0, 2));
            mx1 = fmaxf(mx1, __shfl_xor_sync(0xffffffffu, mx1, 1));
            mx1 = fmaxf(mx1, __shfl_xor_sync(0xffffffffu, mx1, 2));

            const float nm0 = fmaxf(mrow[mt][0], mx0);
            const float nm1 = fmaxf(mrow[mt][1], mx1);
            const float al0 = __expf(mrow[mt][0] - nm0);
            const float al1 = __expf(mrow[mt][1] - nm1);
            mrow[mt][0] = nm0; mrow[mt][1] = nm1;

            float ps0 = 0.f, ps1 = 0.f;
#pragma unroll
            for (int nt = 0; nt < 8; nt++) {
                s[mt][nt][0] = __expf(s[mt][nt][0] - nm0);
                s[mt][nt][1] = __expf(s[mt][nt][1] - nm0);
                s[mt][nt][2] = __expf(s[mt][nt][2] - nm1);
                s[mt][nt][3] = __expf(s[mt][nt][3] - nm1);
                ps0 += s[mt][nt][0] + s[mt][nt][1];
                ps1 += s[mt][nt][2] + s[mt][nt][3];
            }
            ps0 += __shfl_xor_sync(0xffffffffu, ps0, 1);
            ps0 += __shfl_xor_sync(0xffffffffu, ps0, 2);
            ps1 += __shfl_xor_sync(0xffffffffu, ps1, 1);
            ps1 += __shfl_xor_sync(0xffffffffu, ps1, 2);
            lrow[mt][0] = lrow[mt][0] * al0 + ps0;
            lrow[mt][1] = lrow[mt][1] * al1 + ps1;

#pragma unroll
            for (int nt = 0; nt < 8; nt++) {
                o[mt][nt][0] *= al0; o[mt][nt][1] *= al0;
                o[mt][nt][2] *= al1; o[mt][nt][3] *= al1;
            }
        }

#pragma unroll
        for (int ks = 0; ks < 4; ks++) {
            uint32_t pa[2][4];
#pragma unroll
            for (int mt = 0; mt < 2; mt++) {
                pa[mt][0] = pack2(s[mt][2 * ks][0],     s[mt][2 * ks][1]);
                pa[mt][1] = pack2(s[mt][2 * ks][2],     s[mt][2 * ks][3]);
                pa[mt][2] = pack2(s[mt][2 * ks + 1][0], s[mt][2 * ks + 1][1]);
                pa[mt][3] = pack2(s[mt][2 * ks + 1][2], s[mt][2 * ks + 1][3]);
            }
#pragma unroll
            for (int nt = 0; nt < 8; nt++) {
                const uint2 bb = *(const uint2*)&sV[(nt * 8 + g) * VLDH
                                                    + ks * 16 + 4 * tig];
                mma_f16(o[0][nt], pa[0][0], pa[0][1], pa[0][2], pa[0][3], bb.x, bb.y);
                mma_f16(o[1][nt], pa[1][0], pa[1][1], pa[1][2], pa[1][3], bb.x, bb.y);
            }
        }

        __syncthreads();
        if (t + 2 < NTILE) A_ISSUE(t + 2, t & 1);
    }
#undef A_ISSUE

#pragma unroll
    for (int mt = 0; mt < 2; mt++) {
        const float inv0 = 1.f / lrow[mt][0];
        const float inv1 = 1.f / lrow[mt][1];
        const int row = q0 + w * 32 + mt * 16 + g;
#pragma unroll
        for (int nt = 0; nt < 8; nt++) {
            const int dsti = h * HD_ + (nt >> 1) * 16 + 4 * tig + 2 * (nt & 1);
            *(__half2*)(O + (size_t)(b * S_ + row) * D_ + dsti) =
                __floats2half2_rn(o[mt][nt][0] * inv0, o[mt][nt][1] * inv0);
            *(__half2*)(O + (size_t)(b * S_ + row + 8) * D_ + dsti) =
                __floats2half2_rn(o[mt][nt][2] * inv1, o[mt][nt][3] * inv1);
        }
    }
}

// ---------------------------------------------------------------------------
// Launch
// ---------------------------------------------------------------------------
extern "C" void kernel_launch(void* const* d_in, const int* in_sizes, int n_in,
                              void* d_out, int out_size)
{
    const float* x  = (const float*)d_in[0];
    const float* Wq = (const float*)d_in[1];
    const float* Wk = (const float*)d_in[2];
    const float* Wv = (const float*)d_in[3];
    const float* bq = (const float*)d_in[4];
    const float* bk = (const float*)d_in[5];
    const float* bv = (const float*)d_in[6];
    const float* Wo = (const float*)d_in[7];
    const float* bo = (const float*)d_in[8];
    float* out = (float*)d_out;

    __half *xh, *qh, *kh, *vt, *ch, *wqh, *wkh, *wvh, *woh;
    cudaGetSymbolAddress((void**)&xh,  g_xh);
    cudaGetSymbolAddress((void**)&qh,  g_qh);
    cudaGetSymbolAddress((void**)&kh,  g_kh);
    cudaGetSymbolAddress((void**)&vt,  g_vt);
    cudaGetSymbolAddress((void**)&ch,  g_ch);
    cudaGetSymbolAddress((void**)&wqh, g_wq);
    cudaGetSymbolAddress((void**)&wkh, g_wk);
    cudaGetSymbolAddress((void**)&wvh, g_wv);
    cudaGetSymbolAddress((void**)&woh, g_wo);

    cudaFuncSetAttribute(gemm_h,
                         cudaFuncAttributeMaxDynamicSharedMemorySize, GEMM_SMEM);
    cudaFuncSetAttribute(attn_h,
                         cudaFuncAttributeMaxDynamicSharedMemorySize, ATTN_SMEM);

    const int n4all = N4X + 4 * N4W;
    prep_all<<<n4all / 256, 256>>>(x, Wq, Wk, Wv, Wo);

    // fused QKV: z=0 -> q (scale 0.125), z=1 -> k, z=2 -> Vt (key-permuted)
    gemm_h<<<dim3(D_ / GBN, M_TOTAL / GBM, 3), 128, GEMM_SMEM>>>(
        xh, wqh, wkh, wvh, bq, bk, bv, qh, kh, vt, 0);

    attn_h<<<dim3(S_ / 128, H_, B_), 128, ATTN_SMEM>>>(qh, kh, vt, ch);

    // output projection: fp32 plain out
    gemm_h<<<dim3(D_ / GBN, M_TOTAL / GBM, 1), 128, GEMM_SMEM>>>(
        ch, woh, woh, woh, bo, bo, bo, out, out, out, 1);
}

// round 13
// speedup vs baseline: 1.0773x; 1.0773x over previous
#include <cuda_runtime.h>
#include <cuda_fp16.h>
#include <cstdint>
#include <math.h>

// ---------------------------------------------------------------------------
// MultiHeadAttention: B=8, S=1024, D=1024, H=16, HD=64
// Round 13: GEMM reverted to round-11 best (BK=64, stride 80, 2-buffer,
// 128 MMAs/warp/interval). Attention K/V ring -> 4-stage cp.async with a
// single barrier per iteration, staging issued before compute.
// ---------------------------------------------------------------------------

#define B_  8
#define S_  1024
#define D_  1024
#define H_  16
#define HD_ 64
#define M_TOTAL (B_ * S_)          // 8192

__device__ __half g_xh[(size_t)M_TOTAL * D_];
__device__ __half g_qh[(size_t)M_TOTAL * D_];
__device__ __half g_kh[(size_t)M_TOTAL * D_];
__device__ __half g_vt[(size_t)B_ * H_ * HD_ * S_];   // [B][H][d][key-perm]
__device__ __half g_ch[(size_t)M_TOTAL * D_];
__device__ __half g_wq[(size_t)D_ * D_];
__device__ __half g_wk[(size_t)D_ * D_];
__device__ __half g_wv[(size_t)D_ * D_];
__device__ __half g_wo[(size_t)D_ * D_];

// ---------------------------------------------------------------------------
// helpers
// ---------------------------------------------------------------------------
__device__ __forceinline__ uint32_t smem_u32(const void* p) {
    uint32_t a;
    asm("{ .reg .u64 t; cvta.to.shared.u64 t, %1; cvt.u32.u64 %0, t; }"
        : "=r"(a) : "l"(p));
    return a;
}

__device__ __forceinline__ void cpa16(uint32_t dst, const void* src) {
    asm volatile("cp.async.cg.shared.global [%0], [%1], 16;"
                 :: "r"(dst), "l"(src) : "memory");
}
__device__ __forceinline__ void cpa_commit() {
    asm volatile("cp.async.commit_group;" ::: "memory");
}
__device__ __forceinline__ void cpa_wait2() {
    asm volatile("cp.async.wait_group 2;" ::: "memory");
}
__device__ __forceinline__ void cpa_wait1() {
    asm volatile("cp.async.wait_group 1;" ::: "memory");
}
__device__ __forceinline__ void cpa_wait0() {
    asm volatile("cp.async.wait_group 0;" ::: "memory");
}

__device__ __forceinline__ void mma_f16(float* c,
                                        uint32_t a0, uint32_t a1, uint32_t a2, uint32_t a3,
                                        uint32_t b0, uint32_t b1) {
    asm volatile(
        "mma.sync.aligned.m16n8k16.row.col.f32.f16.f16.f32 "
        "{%0,%1,%2,%3}, {%4,%5,%6,%7}, {%8,%9}, {%0,%1,%2,%3};\n"
        : "+f"(c[0]), "+f"(c[1]), "+f"(c[2]), "+f"(c[3])
        : "r"(a0), "r"(a1), "r"(a2), "r"(a3), "r"(b0), "r"(b1));
}

__device__ __forceinline__ uint32_t pack2(float lo, float hi) {
    __half2 h = __floats2half2_rn(lo, hi);
    return *reinterpret_cast<uint32_t*>(&h);
}

// ---------------------------------------------------------------------------
// Fused pre-pass (unchanged)
// ---------------------------------------------------------------------------
#define N4X (M_TOTAL * D_ / 4)     // 2097152
#define N4W (D_ * D_ / 4)          // 262144

__global__ __launch_bounds__(256)
void prep_all(const float* __restrict__ x,
              const float* __restrict__ Wq, const float* __restrict__ Wk,
              const float* __restrict__ Wv, const float* __restrict__ Wo)
{
    const int i = blockIdx.x * blockDim.x + threadIdx.x;
    const float* src;
    __half* dst;
    int j;
    if (i < N4X)                  { src = x;  dst = g_xh; j = i; }
    else {
        const int r = i - N4X;
        const int w = r >> 18;
        j = r & (N4W - 1);
        if      (w == 0) { src = Wq; dst = g_wq; }
        else if (w == 1) { src = Wk; dst = g_wk; }
        else if (w == 2) { src = Wv; dst = g_wv; }
        else             { src = Wo; dst = g_wo; }
    }
    const float4 v = ((const float4*)src)[j];
    const int flat = j << 2;
    const int base = flat & ~15;
    const int u0   = (flat & 15) >> 1;
    const int p0   = ((u0 & 3) << 1) | (u0 >> 2);
    const int u1   = u0 + 1;
    const int p1   = ((u1 & 3) << 1) | (u1 >> 2);
    *(__half2*)(dst + base + 2 * p0) = __floats2half2_rn(v.x, v.y);
    *(__half2*)(dst + base + 2 * p1) = __floats2half2_rn(v.z, v.w);
}

// ---------------------------------------------------------------------------
// fp16 GEMM (NT) — round-11 best config, unchanged:
// CTA 128x128, 128 threads (4 warps of 64x64), BK=64, 2-buffer cp.async,
// 2 CTAs/SM, stride 80 halves (conflict-free), 128 MMAs/warp per interval.
// ---------------------------------------------------------------------------
#define GBM 128
#define GBN 128
#define GBKH 64
#define GLDH 80
#define GBUFH ((GBM + GBN) * GLDH)               // 20480 halves / buffer
#define GEMM_SMEM (2 * GBUFH * 2)                // 81920 bytes

__global__ __launch_bounds__(128, 2)
void gemm_h(const __half* __restrict__ A,
            const __half* __restrict__ W0, const __half* __restrict__ W1,
            const __half* __restrict__ W2,
            const float* __restrict__ bb0, const float* __restrict__ bb1,
            const float* __restrict__ bb2,
            void* C0, void* C1, void* C2,
            int oproj)
{
    extern __shared__ __half smh[];
    const int z = blockIdx.z;
    const __half* Bw   = (z == 0) ? W0  : (z == 1) ? W1  : W2;
    const float*  bias = (z == 0) ? bb0 : (z == 1) ? bb1 : bb2;
    void*         C    = (z == 0) ? C0  : (z == 1) ? C1  : C2;
    const float scale  = (!oproj && z == 0) ? 0.125f : 1.0f;

    const int tid  = threadIdx.x;
    const int wid  = tid >> 5;
    const int lane = tid & 31;
    const int g    = lane >> 2;
    const int tig  = lane & 3;
    const int wm   = (wid & 1) * 64;
    const int wn   = (wid >> 1) * 64;
    const int bm   = blockIdx.y * GBM;
    const int bn   = blockIdx.x * GBN;

    const __half* Abase = A  + (size_t)bm * D_;
    const __half* Bbase = Bw + (size_t)bn * D_;
    const uint32_t su   = smem_u32(smh);

#define G_ISSUE(slab, buf) do {                                            \
        const uint32_t s0 = su + (uint32_t)(buf) * (GBUFH * 2);            \
        const int k0 = (slab) * GBKH;                                      \
        _Pragma("unroll")                                                  \
        for (int j = 0; j < 8; j++) {                                      \
            const int i = tid + 128 * j;      /* A: 1024 16B chunks */     \
            const int row = i >> 3, ch = (i & 7) * 8;                      \
            cpa16(s0 + (row * GLDH + ch) * 2,                              \
                  Abase + (size_t)row * D_ + k0 + ch);                     \
        }                                                                  \
        _Pragma("unroll")                                                  \
        for (int j = 0; j < 8; j++) {                                      \
            const int i = tid + 128 * j;      /* B: 1024 16B chunks */     \
            const int row = i >> 3, ch = (i & 7) * 8;                      \
            cpa16(s0 + ((GBM + row) * GLDH + ch) * 2,                      \
                  Bbase + (size_t)row * D_ + k0 + ch);                     \
        }                                                                  \
        cpa_commit();                                                      \
    } while (0)

    float acc[4][8][4];
#pragma unroll
    for (int mt = 0; mt < 4; mt++)
#pragma unroll
        for (int nt = 0; nt < 8; nt++)
#pragma unroll
            for (int i = 0; i < 4; i++) acc[mt][nt][i] = 0.f;

    const int NT = D_ / GBKH;   // 16
    G_ISSUE(0, 0);
    G_ISSUE(1, 1);

    for (int t = 0; t < NT; t++) {
        if (t == NT - 1) cpa_wait0(); else cpa_wait1();
        __syncthreads();

        const __half* as = smh + (t & 1) * GBUFH;
        const __half* bs = as + GBM * GLDH;
#pragma unroll
        for (int ks = 0; ks < 4; ks++) {
            uint2 alo[4], ahi[4];
#pragma unroll
            for (int mt = 0; mt < 4; mt++) {
                const int r0 = (wm + mt * 16 + g) * GLDH + ks * 16 + 4 * tig;
                alo[mt] = *(const uint2*)&as[r0];
                ahi[mt] = *(const uint2*)&as[r0 + 8 * GLDH];
            }
#pragma unroll
            for (int nt = 0; nt < 8; nt++) {
                const uint2 bb = *(const uint2*)&bs[(wn + nt * 8 + g) * GLDH
                                                    + ks * 16 + 4 * tig];
#pragma unroll
                for (int mt = 0; mt < 4; mt++)
                    mma_f16(acc[mt][nt], alo[mt].x, ahi[mt].x, alo[mt].y, ahi[mt].y,
                            bb.x, bb.y);
            }
        }
        __syncthreads();                 // compute done before reissue
        if (t + 2 < NT) G_ISSUE(t + 2, t & 1);
    }
#undef G_ISSUE

    if (oproj) {
        float* Co = (float*)C;
#pragma unroll
        for (int mt = 0; mt < 4; mt++) {
            const int row0 = bm + wm + mt * 16 + g;
#pragma unroll
            for (int nt = 0; nt < 8; nt++) {
                const int col = bn + wn + nt * 8 + 2 * tig;
                const float c0 = bias[col], c1 = bias[col + 1];
                float2 v0 = make_float2(acc[mt][nt][0] + c0, acc[mt][nt][1] + c1);
                float2 v1 = make_float2(acc[mt][nt][2] + c0, acc[mt][nt][3] + c1);
                *(float2*)(Co + (size_t)row0 * D_ + col)       = v0;
                *(float2*)(Co + (size_t)(row0 + 8) * D_ + col) = v1;
            }
        }
    } else if (z < 2) {
        __half* Ch = (__half*)C;
#pragma unroll
        for (int mt = 0; mt < 4; mt++) {
            const int row0 = bm + wm + mt * 16 + g;
#pragma unroll
            for (int nt = 0; nt < 8; nt++) {
                const int n = bn + wn + nt * 8 + 2 * tig;
                const int dsti = bn + wn + (nt & ~1) * 8 + 4 * tig + 2 * (nt & 1);
                const float c0 = bias[n], c1 = bias[n + 1];
                *(__half2*)(Ch + (size_t)row0 * D_ + dsti) =
                    __floats2half2_rn((acc[mt][nt][0] + c0) * scale,
                                      (acc[mt][nt][1] + c1) * scale);
                *(__half2*)(Ch + (size_t)(row0 + 8) * D_ + dsti) =
                    __floats2half2_rn((acc[mt][nt][2] + c0) * scale,
                                      (acc[mt][nt][3] + c1) * scale);
            }
        }
    } else {
        // transposed Vt output with unit-permuted key positions
        __half* Vt = (__half*)C;
#pragma unroll
        for (int mt = 0; mt < 4; mt++) {
            const int row0 = bm + wm + mt * 16 + g;
#pragma unroll
            for (int nt = 0; nt < 8; nt++) {
                const int n  = bn + wn + nt * 8 + 2 * tig;
                const float c0 = bias[n], c1 = bias[n + 1];
#pragma unroll
                for (int e = 0; e < 4; e++) {
                    const int row = row0 + (e >> 1) * 8;
                    const int col = n + (e & 1);
                    const float val = acc[mt][nt][e] + ((e & 1) ? c1 : c0);
                    const int bIdx = row >> 10, s = row & 1023;
                    const int u    = (s >> 1) & 7;
                    const int sp   = (s & ~15) + 2 * (((u & 3) << 1) | (u >> 2)) + (s & 1);
                    const int head = col >> 6,  dd = col & 63;
                    Vt[(((size_t)(bIdx * H_ + head)) * HD_ + dd) * S_ + sp] =
                        __float2half_rn(val);
                }
            }
        }
    }
}

// ---------------------------------------------------------------------------
// Flash attention: 4-stage cp.async K/V ring, ONE barrier per iteration,
// staging issued before compute. Q frags hoisted; Vt key-permuted LDS.64.
// smem = Q 20KB + 8 x 10KB stages = 100KB -> 2 CTAs/SM.
// ---------------------------------------------------------------------------
#define QLDH 80
#define KLDH 80
#define VLDH 80
#define OFF_K(s) (128 * QLDH + (s) * 64 * KLDH)
#define OFF_V(s) (128 * QLDH + 4 * 64 * KLDH + (s) * 64 * VLDH)
#define ATTN_SMEM ((128 * QLDH + 8 * 64 * KLDH) * 2)   // 102400 B

__global__ __launch_bounds__(128, 2)
void attn_h(const __half* __restrict__ Q, const __half* __restrict__ K,
            const __half* __restrict__ Vt, __half* __restrict__ O)
{
    extern __shared__ __half smh[];
    const uint32_t su = smem_u32(smh);

    const int q0   = blockIdx.x * 128;
    const int h    = blockIdx.y;
    const int b    = blockIdx.z;
    const int tid  = threadIdx.x;
    const int w    = tid >> 5;
    const int lane = tid & 31;
    const int g    = lane >> 2;
    const int tig  = lane & 3;

    const size_t base  = (size_t)b * S_ * D_ + (size_t)h * HD_;
    const size_t vbase = ((size_t)(b * H_ + h)) * HD_ * S_;

#define A_ISSUE(t) do {                                                    \
        const int sbuf = (t) & 3;                                          \
        const __half* Kb = K  + base + (size_t)((t) * 64) * D_;            \
        const __half* Vb = Vt + vbase + (t) * 64;                          \
        _Pragma("unroll")                                                  \
        for (int j = 0; j < 4; j++) {                                      \
            const int i = tid + 128 * j;                                   \
            const int row = i >> 3, ch = (i & 7) * 8;                      \
            cpa16(su + (OFF_K(sbuf) + row * KLDH + ch) * 2,                \
                  Kb + (size_t)row * D_ + ch);                             \
            cpa16(su + (OFF_V(sbuf) + row * VLDH + ch) * 2,                \
                  Vb + (size_t)row * S_ + ch);                             \
        }                                                                  \
        cpa_commit();                                                      \
    } while (0)

    // prologue: group0 = Q + KV tile 0; groups 1,2 = KV tiles 1,2
    {
        const __half* Qb = Q + base + (size_t)q0 * D_;
#pragma unroll
        for (int j = 0; j < 8; j++) {
            const int i = tid + 128 * j;
            const int row = i >> 3, ch = (i & 7) * 8;
            cpa16(su + (row * QLDH + ch) * 2, Qb + (size_t)row * D_ + ch);
        }
        const __half* Kb = K + base;
        const __half* Vb = Vt + vbase;
#pragma unroll
        for (int j = 0; j < 4; j++) {
            const int i = tid + 128 * j;
            const int row = i >> 3, ch = (i & 7) * 8;
            cpa16(su + (OFF_K(0) + row * KLDH + ch) * 2, Kb + (size_t)row * D_ + ch);
            cpa16(su + (OFF_V(0) + row * VLDH + ch) * 2, Vb + (size_t)row * S_ + ch);
        }
        cpa_commit();
        A_ISSUE(1);
        A_ISSUE(2);
    }

    float mrow[2][2], lrow[2][2];
#pragma unroll
    for (int mt = 0; mt < 2; mt++) {
        mrow[mt][0] = -1e30f; mrow[mt][1] = -1e30f;
        lrow[mt][0] = 0.f;    lrow[mt][1] = 0.f;
    }
    float o[2][8][4];
#pragma unroll
    for (int mt = 0; mt < 2; mt++)
#pragma unroll
        for (int nt = 0; nt < 8; nt++)
#pragma unroll
            for (int i = 0; i < 4; i++) o[mt][nt][i] = 0.f;

    uint2 qlo[2][4], qhi[2][4];

    const int NTILE = S_ / 64;   // 16
    for (int t = 0; t < NTILE; t++) {
        // tile t complete when pending <= issued - (t+1); issued = min(t+3,16)
        if (t <= NTILE - 3)      cpa_wait2();
        else if (t == NTILE - 2) cpa_wait1();
        else                     cpa_wait0();
        __syncthreads();     // single barrier: publishes tile t; fences the
                             // upcoming writes to buffer (t+3)&3 against its
                             // last readers (iteration t-1)

        if (t + 3 < NTILE) A_ISSUE(t + 3);   // staging BEFORE compute

        if (t == 0) {
#pragma unroll
            for (int ks = 0; ks < 4; ks++)
#pragma unroll
                for (int mt = 0; mt < 2; mt++) {
                    const int r0 = (w * 32 + mt * 16 + g) * QLDH + ks * 16 + 4 * tig;
                    qlo[mt][ks] = *(const uint2*)&smh[r0];
                    qhi[mt][ks] = *(const uint2*)&smh[r0 + 8 * QLDH];
                }
        }

        const __half* sK = smh + OFF_K(t & 3);
        const __half* sV = smh + OFF_V(t & 3);

        // ---- S = Q . K^T ----
        float s[2][8][4];
#pragma unroll
        for (int mt = 0; mt < 2; mt++)
#pragma unroll
            for (int nt = 0; nt < 8; nt++)
#pragma unroll
                for (int i = 0; i < 4; i++) s[mt][nt][i] = 0.f;

#pragma unroll
        for (int ks = 0; ks < 4; ks++) {
#pragma unroll
            for (int nt = 0; nt < 8; nt++) {
                const uint2 bb = *(const uint2*)&sK[(nt * 8 + g) * KLDH
                                                    + ks * 16 + 4 * tig];
                mma_f16(s[0][nt], qlo[0][ks].x, qhi[0][ks].x, qlo[0][ks].y,
                        qhi[0][ks].y, bb.x, bb.y);
                mma_f16(s[1][nt], qlo[1][ks].x, qhi[1][ks].x, qlo[1][ks].y,
                        qhi[1][ks].y, bb.x, bb.y);
            }
        }

        // ---- online softmax (s -> P in place) ----
#pragma unroll
        for (int mt = 0; mt < 2; mt++) {
            float mx0 = -1e30f, mx1 = -1e30f;
#pragma unroll
            for (int nt = 0; nt < 8; nt++) {
                mx0 = fmaxf(mx0, fmaxf(s[mt][nt][0], s[mt][nt][1]));
                mx1 = fmaxf(mx1, fmaxf(s[mt][nt][2], s[mt][nt][3]));
            }
            mx0 = fmaxf(mx0, __shfl_xor_sync(0xffffffffu, mx0, 1));
            mx0 = fmaxf(mx0, __shfl_xor_sync(0xffffffffu, mx0, 2));
            mx1 = fmaxf(mx1, __shfl_xor_sync(0xffffffffu, mx1, 1));
            mx1 = fmaxf(mx1, __shfl_xor_sync(0xffffffffu, mx1, 2));

            const float nm0 = fmaxf(mrow[mt][0], mx0);
            const float nm1 = fmaxf(mrow[mt][1], mx1);
            const float al0 = __expf(mrow[mt][0] - nm0);
            const float al1 = __expf(mrow[mt][1] - nm1);
            mrow[mt][0] = nm0; mrow[mt][1] = nm1;

            float ps0 = 0.f, ps1 = 0.f;
#pragma unroll
            for (int nt = 0; nt < 8; nt++) {
                s[mt][nt][0] = __expf(s[mt][nt][0] - nm0);
                s[mt][nt][1] = __expf(s[mt][nt][1] - nm0);
                s[mt][nt][2] = __expf(s[mt][nt][2] - nm1);
                s[mt][nt][3] = __expf(s[mt][nt][3] - nm1);
                ps0 += s[mt][nt][0] + s[mt][nt][1];
                ps1 += s[mt][nt][2] + s[mt][nt][3];
            }
            ps0 += __shfl_xor_sync(0xffffffffu, ps0, 1);
            ps0 += __shfl_xor_sync(0xffffffffu, ps0, 2);
            ps1 += __shfl_xor_sync(0xffffffffu, ps1, 1);
            ps1 += __shfl_xor_sync(0xffffffffu, ps1, 2);
            lrow[mt][0] = lrow[mt][0] * al0 + ps0;
            lrow[mt][1] = lrow[mt][1] * al1 + ps1;

#pragma unroll
            for (int nt = 0; nt < 8; nt++) {
                o[mt][nt][0] *= al0; o[mt][nt][1] *= al0;
                o[mt][nt][2] *= al1; o[mt][nt][3] *= al1;
            }
        }

        // ---- O += P . V ----
#pragma unroll
        for (int ks = 0; ks < 4; ks++) {
            uint32_t pa[2][4];
#pragma unroll
            for (int mt = 0; mt < 2; mt++) {
                pa[mt][0] = pack2(s[mt][2 * ks][0],     s[mt][2 * ks][1]);
                pa[mt][1] = pack2(s[mt][2 * ks][2],     s[mt][2 * ks][3]);
                pa[mt][2] = pack2(s[mt][2 * ks + 1][0], s[mt][2 * ks + 1][1]);
                pa[mt][3] = pack2(s[mt][2 * ks + 1][2], s[mt][2 * ks + 1][3]);
            }
#pragma unroll
            for (int nt = 0; nt < 8; nt++) {
                const uint2 bb = *(const uint2*)&sV[(nt * 8 + g) * VLDH
                                                    + ks * 16 + 4 * tig];
                mma_f16(o[0][nt], pa[0][0], pa[0][1], pa[0][2], pa[0][3], bb.x, bb.y);
                mma_f16(o[1][nt], pa[1][0], pa[1][1], pa[1][2], pa[1][3], bb.x, bb.y);
            }
        }
    }
#undef A_ISSUE

#pragma unroll
    for (int mt = 0; mt < 2; mt++) {
        const float inv0 = 1.f / lrow[mt][0];
        const float inv1 = 1.f / lrow[mt][1];
        const int row = q0 + w * 32 + mt * 16 + g;
#pragma unroll
        for (int nt = 0; nt < 8; nt++) {
            const int dsti = h * HD_ + (nt >> 1) * 16 + 4 * tig + 2 * (nt & 1);
            *(__half2*)(O + (size_t)(b * S_ + row) * D_ + dsti) =
                __floats2half2_rn(o[mt][nt][0] * inv0, o[mt][nt][1] * inv0);
            *(__half2*)(O + (size_t)(b * S_ + row + 8) * D_ + dsti) =
                __floats2half2_rn(o[mt][nt][2] * inv1, o[mt][nt][3] * inv1);
        }
    }
}

// ---------------------------------------------------------------------------
// Launch
// ---------------------------------------------------------------------------
extern "C" void kernel_launch(void* const* d_in, const int* in_sizes, int n_in,
                              void* d_out, int out_size)
{
    const float* x  = (const float*)d_in[0];
    const float* Wq = (const float*)d_in[1];
    const float* Wk = (const float*)d_in[2];
    const float* Wv = (const float*)d_in[3];
    const float* bq = (const float*)d_in[4];
    const float* bk = (const float*)d_in[5];
    const float* bv = (const float*)d_in[6];
    const float* Wo = (const float*)d_in[7];
    const float* bo = (const float*)d_in[8];
    float* out = (float*)d_out;

    __half *xh, *qh, *kh, *vt, *ch, *wqh, *wkh, *wvh, *woh;
    cudaGetSymbolAddress((void**)&xh,  g_xh);
    cudaGetSymbolAddress((void**)&qh,  g_qh);
    cudaGetSymbolAddress((void**)&kh,  g_kh);
    cudaGetSymbolAddress((void**)&vt,  g_vt);
    cudaGetSymbolAddress((void**)&ch,  g_ch);
    cudaGetSymbolAddress((void**)&wqh, g_wq);
    cudaGetSymbolAddress((void**)&wkh, g_wk);
    cudaGetSymbolAddress((void**)&wvh, g_wv);
    cudaGetSymbolAddress((void**)&woh, g_wo);

    cudaFuncSetAttribute(gemm_h,
                         cudaFuncAttributeMaxDynamicSharedMemorySize, GEMM_SMEM);
    cudaFuncSetAttribute(attn_h,
                         cudaFuncAttributeMaxDynamicSharedMemorySize, ATTN_SMEM);

    const int n4all = N4X + 4 * N4W;
    prep_all<<<n4all / 256, 256>>>(x, Wq, Wk, Wv, Wo);

    // fused QKV: z=0 -> q (scale 0.125), z=1 -> k, z=2 -> Vt (key-permuted)
    gemm_h<<<dim3(D_ / GBN, M_TOTAL / GBM, 3), 128, GEMM_SMEM>>>(
        xh, wqh, wkh, wvh, bq, bk, bv, qh, kh, vt, 0);

    attn_h<<<dim3(S_ / 128, H_, B_), 128, ATTN_SMEM>>>(qh, kh, vt, ch);

    // output projection: fp32 plain out
    gemm_h<<<dim3(D_ / GBN, M_TOTAL / GBM, 1), 128, GEMM_SMEM>>>(
        ch, woh, woh, woh, bo, bo, bo, out, out, out, 1);
}

// round 14
// speedup vs baseline: 1.1349x; 1.0535x over previous
#include <cuda_runtime.h>
#include <cuda_fp16.h>
#include <cstdint>
#include <math.h>

// ---------------------------------------------------------------------------
// MultiHeadAttention: B=8, S=1024, D=1024, H=16, HD=64
// Round 14: GEMM fragment loads via ldmatrix.x4 (half the shared-load
// instructions), natural-order operands (prep = pure cvt), stride 72
// (ldmatrix conflict-free). Attention unchanged except unpermuted output.
// ---------------------------------------------------------------------------

#define B_  8
#define S_  1024
#define D_  1024
#define H_  16
#define HD_ 64
#define M_TOTAL (B_ * S_)          // 8192

__device__ __half g_xh[(size_t)M_TOTAL * D_];
__device__ __half g_qh[(size_t)M_TOTAL * D_];
__device__ __half g_kh[(size_t)M_TOTAL * D_];
__device__ __half g_vt[(size_t)B_ * H_ * HD_ * S_];   // [B][H][d][key-perm]
__device__ __half g_ch[(size_t)M_TOTAL * D_];
__device__ __half g_wq[(size_t)D_ * D_];
__device__ __half g_wk[(size_t)D_ * D_];
__device__ __half g_wv[(size_t)D_ * D_];
__device__ __half g_wo[(size_t)D_ * D_];

// ---------------------------------------------------------------------------
// helpers
// ---------------------------------------------------------------------------
__device__ __forceinline__ uint32_t smem_u32(const void* p) {
    uint32_t a;
    asm("{ .reg .u64 t; cvta.to.shared.u64 t, %1; cvt.u32.u64 %0, t; }"
        : "=r"(a) : "l"(p));
    return a;
}

__device__ __forceinline__ void cpa16(uint32_t dst, const void* src) {
    asm volatile("cp.async.cg.shared.global [%0], [%1], 16;"
                 :: "r"(dst), "l"(src) : "memory");
}
__device__ __forceinline__ void cpa_commit() {
    asm volatile("cp.async.commit_group;" ::: "memory");
}
__device__ __forceinline__ void cpa_wait2() {
    asm volatile("cp.async.wait_group 2;" ::: "memory");
}
__device__ __forceinline__ void cpa_wait1() {
    asm volatile("cp.async.wait_group 1;" ::: "memory");
}
__device__ __forceinline__ void cpa_wait0() {
    asm volatile("cp.async.wait_group 0;" ::: "memory");
}

__device__ __forceinline__ void mma_f16(float* c,
                                        uint32_t a0, uint32_t a1, uint32_t a2, uint32_t a3,
                                        uint32_t b0, uint32_t b1) {
    asm volatile(
        "mma.sync.aligned.m16n8k16.row.col.f32.f16.f16.f32 "
        "{%0,%1,%2,%3}, {%4,%5,%6,%7}, {%8,%9}, {%0,%1,%2,%3};\n"
        : "+f"(c[0]), "+f"(c[1]), "+f"(c[2]), "+f"(c[3])
        : "r"(a0), "r"(a1), "r"(a2), "r"(a3), "r"(b0), "r"(b1));
}

__device__ __forceinline__ void ldsm_x4(uint32_t& r0, uint32_t& r1,
                                        uint32_t& r2, uint32_t& r3, uint32_t addr) {
    asm volatile("ldmatrix.sync.aligned.m8n8.x4.shared.b16 {%0,%1,%2,%3}, [%4];"
                 : "=r"(r0), "=r"(r1), "=r"(r2), "=r"(r3) : "r"(addr));
}

__device__ __forceinline__ uint32_t pack2(float lo, float hi) {
    __half2 h = __floats2half2_rn(lo, hi);
    return *reinterpret_cast<uint32_t*>(&h);
}

// ---------------------------------------------------------------------------
// Fused pre-pass: pure fp32 -> fp16 convert, natural order (no permutation;
// GEMM uses ldmatrix which requires natural k layout).
// ---------------------------------------------------------------------------
#define N4X (M_TOTAL * D_ / 4)     // 2097152
#define N4W (D_ * D_ / 4)          // 262144

__global__ __launch_bounds__(256)
void prep_all(const float* __restrict__ x,
              const float* __restrict__ Wq, const float* __restrict__ Wk,
              const float* __restrict__ Wv, const float* __restrict__ Wo)
{
    const int i = blockIdx.x * blockDim.x + threadIdx.x;
    const float* src;
    __half* dst;
    int j;
    if (i < N4X)                  { src = x;  dst = g_xh; j = i; }
    else {
        const int r = i - N4X;
        const int w = r >> 18;
        j = r & (N4W - 1);
        if      (w == 0) { src = Wq; dst = g_wq; }
        else if (w == 1) { src = Wk; dst = g_wk; }
        else if (w == 2) { src = Wv; dst = g_wv; }
        else             { src = Wo; dst = g_wo; }
    }
    const float4 v = ((const float4*)src)[j];
    const int flat = j << 2;
    *(__half2*)(dst + flat)     = __floats2half2_rn(v.x, v.y);
    *(__half2*)(dst + flat + 2) = __floats2half2_rn(v.z, v.w);
}

// ---------------------------------------------------------------------------
// fp16 GEMM (NT): CTA 128x128, 128 threads (4 warps of 64x64), BK=64,
// 2-buffer cp.async, 2 CTAs/SM. Stride 72 halves: ldmatrix-conflict-free
// (8 consecutive rows -> word banks 4r mod 32, all distinct).
// Fragments via ldmatrix.x4: 8 instrs per ks (was 16 LDS.64).
// ---------------------------------------------------------------------------
#define GBM 128
#define GBN 128
#define GBKH 64
#define GLDH 72
#define GBUFH ((GBM + GBN) * GLDH)               // 18432 halves / buffer
#define GEMM_SMEM (2 * GBUFH * 2)                // 73728 bytes
#define MT_STRIDE (16 * GLDH * 2)                // 2304 bytes per 16 rows

__global__ __launch_bounds__(128, 2)
void gemm_h(const __half* __restrict__ A,
            const __half* __restrict__ W0, const __half* __restrict__ W1,
            const __half* __restrict__ W2,
            const float* __restrict__ bb0, const float* __restrict__ bb1,
            const float* __restrict__ bb2,
            void* C0, void* C1, void* C2,
            int oproj)
{
    extern __shared__ __half smh[];
    const int z = blockIdx.z;
    const __half* Bw   = (z == 0) ? W0  : (z == 1) ? W1  : W2;
    const float*  bias = (z == 0) ? bb0 : (z == 1) ? bb1 : bb2;
    void*         C    = (z == 0) ? C0  : (z == 1) ? C1  : C2;
    const float scale  = (!oproj && z == 0) ? 0.125f : 1.0f;

    const int tid  = threadIdx.x;
    const int wid  = tid >> 5;
    const int lane = tid & 31;
    const int g    = lane >> 2;
    const int tig  = lane & 3;
    const int wm   = (wid & 1) * 64;
    const int wn   = (wid >> 1) * 64;
    const int bm   = blockIdx.y * GBM;
    const int bn   = blockIdx.x * GBN;

    const __half* Abase = A  + (size_t)bm * D_;
    const __half* Bbase = Bw + (size_t)bn * D_;
    const uint32_t su   = smem_u32(smh);

    // ldmatrix per-lane address bases (byte offsets within a buffer)
    const int lrow8 = lane & 7;
    const int lgrp  = lane >> 3;    // 0..3
    // A x4 groups: [m0-7,k0][m8-15,k0][m0-7,k+8][m8-15,k+8] -> a0,a1,a2,a3
    const uint32_t aoff =
        ((wm + (lgrp & 1) * 8 + lrow8) * GLDH + (lgrp >> 1) * 8) * 2;
    // B x4 groups: [nt0,k0][nt0,k+8][nt1,k0][nt1,k+8] -> b0,b1 of nt0, nt1
    const uint32_t boff =
        ((GBM + wn + (lgrp >> 1) * 8 + lrow8) * GLDH + (lgrp & 1) * 8) * 2;

#define G_ISSUE(slab, buf) do {                                            \
        const uint32_t s0 = su + (uint32_t)(buf) * (GBUFH * 2);            \
        const int k0 = (slab) * GBKH;                                      \
        _Pragma("unroll")                                                  \
        for (int j = 0; j < 8; j++) {                                      \
            const int i = tid + 128 * j;      /* A: 1024 16B chunks */     \
            const int row = i >> 3, ch = (i & 7) * 8;                      \
            cpa16(s0 + (row * GLDH + ch) * 2,                              \
                  Abase + (size_t)row * D_ + k0 + ch);                     \
        }                                                                  \
        _Pragma("unroll")                                                  \
        for (int j = 0; j < 8; j++) {                                      \
            const int i = tid + 128 * j;      /* B: 1024 16B chunks */     \
            const int row = i >> 3, ch = (i & 7) * 8;                      \
            cpa16(s0 + ((GBM + row) * GLDH + ch) * 2,                      \
                  Bbase + (size_t)row * D_ + k0 + ch);                     \
        }                                                                  \
        cpa_commit();                                                      \
    } while (0)

    float acc[4][8][4];
#pragma unroll
    for (int mt = 0; mt < 4; mt++)
#pragma unroll
        for (int nt = 0; nt < 8; nt++)
#pragma unroll
            for (int i = 0; i < 4; i++) acc[mt][nt][i] = 0.f;

    const int NT = D_ / GBKH;   // 16
    G_ISSUE(0, 0);
    G_ISSUE(1, 1);

    for (int t = 0; t < NT; t++) {
        if (t == NT - 1) cpa_wait0(); else cpa_wait1();
        __syncthreads();

        const uint32_t sbuf = su + (uint32_t)(t & 1) * (GBUFH * 2);
#pragma unroll
        for (int ks = 0; ks < 4; ks++) {
            uint32_t af[4][4];
#pragma unroll
            for (int mt = 0; mt < 4; mt++)
                ldsm_x4(af[mt][0], af[mt][1], af[mt][2], af[mt][3],
                        sbuf + aoff + mt * MT_STRIDE + ks * 32);
            uint32_t bfr[8][2];
#pragma unroll
            for (int p = 0; p < 4; p++)
                ldsm_x4(bfr[2 * p][0], bfr[2 * p][1],
                        bfr[2 * p + 1][0], bfr[2 * p + 1][1],
                        sbuf + boff + p * MT_STRIDE + ks * 32);
#pragma unroll
            for (int nt = 0; nt < 8; nt++)
#pragma unroll
                for (int mt = 0; mt < 4; mt++)
                    mma_f16(acc[mt][nt], af[mt][0], af[mt][1], af[mt][2], af[mt][3],
                            bfr[nt][0], bfr[nt][1]);
        }
        __syncthreads();                 // compute done before reissue
        if (t + 2 < NT) G_ISSUE(t + 2, t & 1);
    }
#undef G_ISSUE

    if (oproj) {
        float* Co = (float*)C;
#pragma unroll
        for (int mt = 0; mt < 4; mt++) {
            const int row0 = bm + wm + mt * 16 + g;
#pragma unroll
            for (int nt = 0; nt < 8; nt++) {
                const int col = bn + wn + nt * 8 + 2 * tig;
                const float c0 = bias[col], c1 = bias[col + 1];
                float2 v0 = make_float2(acc[mt][nt][0] + c0, acc[mt][nt][1] + c1);
                float2 v1 = make_float2(acc[mt][nt][2] + c0, acc[mt][nt][3] + c1);
                *(float2*)(Co + (size_t)row0 * D_ + col)       = v0;
                *(float2*)(Co + (size_t)(row0 + 8) * D_ + col) = v1;
            }
        }
    } else if (z < 2) {
        // q/k outputs: unit-permuted in head-dim (attention's LDS.64 frags)
        __half* Ch = (__half*)C;
#pragma unroll
        for (int mt = 0; mt < 4; mt++) {
            const int row0 = bm + wm + mt * 16 + g;
#pragma unroll
            for (int nt = 0; nt < 8; nt++) {
                const int n = bn + wn + nt * 8 + 2 * tig;
                const int dsti = bn + wn + (nt & ~1) * 8 + 4 * tig + 2 * (nt & 1);
                const float c0 = bias[n], c1 = bias[n + 1];
                *(__half2*)(Ch + (size_t)row0 * D_ + dsti) =
                    __floats2half2_rn((acc[mt][nt][0] + c0) * scale,
                                      (acc[mt][nt][1] + c1) * scale);
                *(__half2*)(Ch + (size_t)(row0 + 8) * D_ + dsti) =
                    __floats2half2_rn((acc[mt][nt][2] + c0) * scale,
                                      (acc[mt][nt][3] + c1) * scale);
            }
        }
    } else {
        // transposed Vt output with unit-permuted key positions
        __half* Vt = (__half*)C;
#pragma unroll
        for (int mt = 0; mt < 4; mt++) {
            const int row0 = bm + wm + mt * 16 + g;
#pragma unroll
            for (int nt = 0; nt < 8; nt++) {
                const int n  = bn + wn + nt * 8 + 2 * tig;
                const float c0 = bias[n], c1 = bias[n + 1];
#pragma unroll
                for (int e = 0; e < 4; e++) {
                    const int row = row0 + (e >> 1) * 8;
                    const int col = n + (e & 1);
                    const float val = acc[mt][nt][e] + ((e & 1) ? c1 : c0);
                    const int bIdx = row >> 10, s = row & 1023;
                    const int u    = (s >> 1) & 7;
                    const int sp   = (s & ~15) + 2 * (((u & 3) << 1) | (u >> 2)) + (s & 1);
                    const int head = col >> 6,  dd = col & 63;
                    Vt[(((size_t)(bIdx * H_ + head)) * HD_ + dd) * S_ + sp] =
                        __float2half_rn(val);
                }
            }
        }
    }
}

// ---------------------------------------------------------------------------
// Flash attention (round 13): 4-stage cp.async K/V ring, single barrier per
// iteration, staging before compute. Q frags hoisted; Vt key-permuted.
// Output ch now written UNpermuted (O-proj uses ldmatrix / natural order).
// ---------------------------------------------------------------------------
#define QLDH 80
#define KLDH 80
#define VLDH 80
#define OFF_K(s) (128 * QLDH + (s) * 64 * KLDH)
#define OFF_V(s) (128 * QLDH + 4 * 64 * KLDH + (s) * 64 * VLDH)
#define ATTN_SMEM ((128 * QLDH + 8 * 64 * KLDH) * 2)   // 102400 B

__global__ __launch_bounds__(128, 2)
void attn_h(const __half* __restrict__ Q, const __half* __restrict__ K,
            const __half* __restrict__ Vt, __half* __restrict__ O)
{
    extern __shared__ __half smh[];
    const uint32_t su = smem_u32(smh);

    const int q0   = blockIdx.x * 128;
    const int h    = blockIdx.y;
    const int b    = blockIdx.z;
    const int tid  = threadIdx.x;
    const int w    = tid >> 5;
    const int lane = tid & 31;
    const int g    = lane >> 2;
    const int tig  = lane & 3;

    const size_t base  = (size_t)b * S_ * D_ + (size_t)h * HD_;
    const size_t vbase = ((size_t)(b * H_ + h)) * HD_ * S_;

#define A_ISSUE(t) do {                                                    \
        const int sbuf = (t) & 3;                                          \
        const __half* Kb = K  + base + (size_t)((t) * 64) * D_;            \
        const __half* Vb = Vt + vbase + (t) * 64;                          \
        _Pragma("unroll")                                                  \
        for (int j = 0; j < 4; j++) {                                      \
            const int i = tid + 128 * j;                                   \
            const int row = i >> 3, ch = (i & 7) * 8;                      \
            cpa16(su + (OFF_K(sbuf) + row * KLDH + ch) * 2,                \
                  Kb + (size_t)row * D_ + ch);                             \
            cpa16(su + (OFF_V(sbuf) + row * VLDH + ch) * 2,                \
                  Vb + (size_t)row * S_ + ch);                             \
        }                                                                  \
        cpa_commit();                                                      \
    } while (0)

    {
        const __half* Qb = Q + base + (size_t)q0 * D_;
#pragma unroll
        for (int j = 0; j < 8; j++) {
            const int i = tid + 128 * j;
            const int row = i >> 3, ch = (i & 7) * 8;
            cpa16(su + (row * QLDH + ch) * 2, Qb + (size_t)row * D_ + ch);
        }
        const __half* Kb = K + base;
        const __half* Vb = Vt + vbase;
#pragma unroll
        for (int j = 0; j < 4; j++) {
            const int i = tid + 128 * j;
            const int row = i >> 3, ch = (i & 7) * 8;
            cpa16(su + (OFF_K(0) + row * KLDH + ch) * 2, Kb + (size_t)row * D_ + ch);
            cpa16(su + (OFF_V(0) + row * VLDH + ch) * 2, Vb + (size_t)row * S_ + ch);
        }
        cpa_commit();
        A_ISSUE(1);
        A_ISSUE(2);
    }

    float mrow[2][2], lrow[2][2];
#pragma unroll
    for (int mt = 0; mt < 2; mt++) {
        mrow[mt][0] = -1e30f; mrow[mt][1] = -1e30f;
        lrow[mt][0] = 0.f;    lrow[mt][1] = 0.f;
    }
    float o[2][8][4];
#pragma unroll
    for (int mt = 0; mt < 2; mt++)
#pragma unroll
        for (int nt = 0; nt < 8; nt++)
#pragma unroll
            for (int i = 0; i < 4; i++) o[mt][nt][i] = 0.f;

    uint2 qlo[2][4], qhi[2][4];

    const int NTILE = S_ / 64;   // 16
    for (int t = 0; t < NTILE; t++) {
        if (t <= NTILE - 3)      cpa_wait2();
        else if (t == NTILE - 2) cpa_wait1();
        else                     cpa_wait0();
        __syncthreads();

        if (t + 3 < NTILE) A_ISSUE(t + 3);

        if (t == 0) {
#pragma unroll
            for (int ks = 0; ks < 4; ks++)
#pragma unroll
                for (int mt = 0; mt < 2; mt++) {
                    const int r0 = (w * 32 + mt * 16 + g) * QLDH + ks * 16 + 4 * tig;
                    qlo[mt][ks] = *(const uint2*)&smh[r0];
                    qhi[mt][ks] = *(const uint2*)&smh[r0 + 8 * QLDH];
                }
        }

        const __half* sK = smh + OFF_K(t & 3);
        const __half* sV = smh + OFF_V(t & 3);

        float s[2][8][4];
#pragma unroll
        for (int mt = 0; mt < 2; mt++)
#pragma unroll
            for (int nt = 0; nt < 8; nt++)
#pragma unroll
                for (int i = 0; i < 4; i++) s[mt][nt][i] = 0.f;

#pragma unroll
        for (int ks = 0; ks < 4; ks++) {
#pragma unroll
            for (int nt = 0; nt < 8; nt++) {
                const uint2 bb = *(const uint2*)&sK[(nt * 8 + g) * KLDH
                                                    + ks * 16 + 4 * tig];
                mma_f16(s[0][nt], qlo[0][ks].x, qhi[0][ks].x, qlo[0][ks].y,
                        qhi[0][ks].y, bb.x, bb.y);
                mma_f16(s[1][nt], qlo[1][ks].x, qhi[1][ks].x, qlo[1][ks].y,
                        qhi[1][ks].y, bb.x, bb.y);
            }
        }

#pragma unroll
        for (int mt = 0; mt < 2; mt++) {
            float mx0 = -1e30f, mx1 = -1e30f;
#pragma unroll
            for (int nt = 0; nt < 8; nt++) {
                mx0 = fmaxf(mx0, fmaxf(s[mt][nt][0], s[mt][nt][1]));
                mx1 = fmaxf(mx1, fmaxf(s[mt][nt][2], s[mt][nt][3]));
            }
            mx0 = fmaxf(mx0, __shfl_xor_sync(0xffffffffu, mx0, 1));
            mx0 = fmaxf(mx0, __shfl_xor_sync(0xffffffffu, mx0, 2));
            mx1 = fmaxf(mx1, __shfl_xor_sync(0xffffffffu, mx1, 1));
            mx1 = fmaxf(mx1, __shfl_xor_sync(0xffffffffu, mx1, 2));

            const float nm0 = fmaxf(mrow[mt][0], mx0);
            const float nm1 = fmaxf(mrow[mt][1], mx1);
            const float al0 = __expf(mrow[mt][0] - nm0);
            const float al1 = __expf(mrow[mt][1] - nm1);
            mrow[mt][0] = nm0; mrow[mt][1] = nm1;

            float ps0 = 0.f, ps1 = 0.f;
#pragma unroll
            for (int nt = 0; nt < 8; nt++) {
                s[mt][nt][0] = __expf(s[mt][nt][0] - nm0);
                s[mt][nt][1] = __expf(s[mt][nt][1] - nm0);
                s[mt][nt][2] = __expf(s[mt][nt][2] - nm1);
                s[mt][nt][3] = __expf(s[mt][nt][3] - nm1);
                ps0 += s[mt][nt][0] + s[mt][nt][1];
                ps1 += s[mt][nt][2] + s[mt][nt][3];
            }
            ps0 += __shfl_xor_sync(0xffffffffu, ps0, 1);
            ps0 += __shfl_xor_sync(0xffffffffu, ps0, 2);
            ps1 += __shfl_xor_sync(0xffffffffu, ps1, 1);
            ps1 += __shfl_xor_sync(0xffffffffu, ps1, 2);
            lrow[mt][0] = lrow[mt][0] * al0 + ps0;
            lrow[mt][1] = lrow[mt][1] * al1 + ps1;

#pragma unroll
            for (int nt = 0; nt < 8; nt++) {
                o[mt][nt][0] *= al0; o[mt][nt][1] *= al0;
                o[mt][nt][2] *= al1; o[mt][nt][3] *= al1;
            }
        }

#pragma unroll
        for (int ks = 0; ks < 4; ks++) {
            uint32_t pa[2][4];
#pragma unroll
            for (int mt = 0; mt < 2; mt++) {
                pa[mt][0] = pack2(s[mt][2 * ks][0],     s[mt][2 * ks][1]);
                pa[mt][1] = pack2(s[mt][2 * ks][2],     s[mt][2 * ks][3]);
                pa[mt][2] = pack2(s[mt][2 * ks + 1][0], s[mt][2 * ks + 1][1]);
                pa[mt][3] = pack2(s[mt][2 * ks + 1][2], s[mt][2 * ks + 1][3]);
            }
#pragma unroll
            for (int nt = 0; nt < 8; nt++) {
                const uint2 bb = *(const uint2*)&sV[(nt * 8 + g) * VLDH
                                                    + ks * 16 + 4 * tig];
                mma_f16(o[0][nt], pa[0][0], pa[0][1], pa[0][2], pa[0][3], bb.x, bb.y);
                mma_f16(o[1][nt], pa[1][0], pa[1][1], pa[1][2], pa[1][3], bb.x, bb.y);
            }
        }
    }
#undef A_ISSUE

    // ---- write out fp16, natural (unpermuted) head-dim for ldmatrix O-proj
#pragma unroll
    for (int mt = 0; mt < 2; mt++) {
        const float inv0 = 1.f / lrow[mt][0];
        const float inv1 = 1.f / lrow[mt][1];
        const int row = q0 + w * 32 + mt * 16 + g;
#pragma unroll
        for (int nt = 0; nt < 8; nt++) {
            const int dsti = h * HD_ + nt * 8 + 2 * tig;
            *(__half2*)(O + (size_t)(b * S_ + row) * D_ + dsti) =
                __floats2half2_rn(o[mt][nt][0] * inv0, o[mt][nt][1] * inv0);
            *(__half2*)(O + (size_t)(b * S_ + row + 8) * D_ + dsti) =
                __floats2half2_rn(o[mt][nt][2] * inv1, o[mt][nt][3] * inv1);
        }
    }
}

// ---------------------------------------------------------------------------
// Launch
// ---------------------------------------------------------------------------
extern "C" void kernel_launch(void* const* d_in, const int* in_sizes, int n_in,
                              void* d_out, int out_size)
{
    const float* x  = (const float*)d_in[0];
    const float* Wq = (const float*)d_in[1];
    const float* Wk = (const float*)d_in[2];
    const float* Wv = (const float*)d_in[3];
    const float* bq = (const float*)d_in[4];
    const float* bk = (const float*)d_in[5];
    const float* bv = (const float*)d_in[6];
    const float* Wo = (const float*)d_in[7];
    const float* bo = (const float*)d_in[8];
    float* out = (float*)d_out;

    __half *xh, *qh, *kh, *vt, *ch, *wqh, *wkh, *wvh, *woh;
    cudaGetSymbolAddress((void**)&xh,  g_xh);
    cudaGetSymbolAddress((void**)&qh,  g_qh);
    cudaGetSymbolAddress((void**)&kh,  g_kh);
    cudaGetSymbolAddress((void**)&vt,  g_vt);
    cudaGetSymbolAddress((void**)&ch,  g_ch);
    cudaGetSymbolAddress((void**)&wqh, g_wq);
    cudaGetSymbolAddress((void**)&wkh, g_wk);
    cudaGetSymbolAddress((void**)&wvh, g_wv);
    cudaGetSymbolAddress((void**)&woh, g_wo);

    cudaFuncSetAttribute(gemm_h,
                         cudaFuncAttributeMaxDynamicSharedMemorySize, GEMM_SMEM);
    cudaFuncSetAttribute(attn_h,
                         cudaFuncAttributeMaxDynamicSharedMemorySize, ATTN_SMEM);

    const int n4all = N4X + 4 * N4W;
    prep_all<<<n4all / 256, 256>>>(x, Wq, Wk, Wv, Wo);

    // fused QKV: z=0 -> q (scale 0.125), z=1 -> k, z=2 -> Vt (key-permuted)
    gemm_h<<<dim3(D_ / GBN, M_TOTAL / GBM, 3), 128, GEMM_SMEM>>>(
        xh, wqh, wkh, wvh, bq, bk, bv, qh, kh, vt, 0);

    attn_h<<<dim3(S_ / 128, H_, B_), 128, ATTN_SMEM>>>(qh, kh, vt, ch);

    // output projection: fp32 plain out
    gemm_h<<<dim3(D_ / GBN, M_TOTAL / GBM, 1), 128, GEMM_SMEM>>>(
        ch, woh, woh, woh, bo, bo, bo, out, out, out, 1);
}

// round 15
// speedup vs baseline: 1.1773x; 1.0374x over previous
#include <cuda_runtime.h>
#include <cuda_fp16.h>
#include <cstdint>
#include <math.h>

// ---------------------------------------------------------------------------
// MultiHeadAttention: B=8, S=1024, D=1024, H=16, HD=64
// Round 15: GEMM = ldmatrix fragments (round-14 win) + 8 warps / 256 threads
// (32x64 warp tiles, acc=64 regs) for 4 warps/SMSP latency hiding.
// BK=64, stride 72, 2-buffer cp.async, 2 CTAs/SM. Attention/prep unchanged.
// ---------------------------------------------------------------------------

#define B_  8
#define S_  1024
#define D_  1024
#define H_  16
#define HD_ 64
#define M_TOTAL (B_ * S_)          // 8192

__device__ __half g_xh[(size_t)M_TOTAL * D_];
__device__ __half g_qh[(size_t)M_TOTAL * D_];
__device__ __half g_kh[(size_t)M_TOTAL * D_];
__device__ __half g_vt[(size_t)B_ * H_ * HD_ * S_];   // [B][H][d][key-perm]
__device__ __half g_ch[(size_t)M_TOTAL * D_];
__device__ __half g_wq[(size_t)D_ * D_];
__device__ __half g_wk[(size_t)D_ * D_];
__device__ __half g_wv[(size_t)D_ * D_];
__device__ __half g_wo[(size_t)D_ * D_];

// ---------------------------------------------------------------------------
// helpers
// ---------------------------------------------------------------------------
__device__ __forceinline__ uint32_t smem_u32(const void* p) {
    uint32_t a;
    asm("{ .reg .u64 t; cvta.to.shared.u64 t, %1; cvt.u32.u64 %0, t; }"
        : "=r"(a) : "l"(p));
    return a;
}

__device__ __forceinline__ void cpa16(uint32_t dst, const void* src) {
    asm volatile("cp.async.cg.shared.global [%0], [%1], 16;"
                 :: "r"(dst), "l"(src) : "memory");
}
__device__ __forceinline__ void cpa_commit() {
    asm volatile("cp.async.commit_group;" ::: "memory");
}
__device__ __forceinline__ void cpa_wait2() {
    asm volatile("cp.async.wait_group 2;" ::: "memory");
}
__device__ __forceinline__ void cpa_wait1() {
    asm volatile("cp.async.wait_group 1;" ::: "memory");
}
__device__ __forceinline__ void cpa_wait0() {
    asm volatile("cp.async.wait_group 0;" ::: "memory");
}

__device__ __forceinline__ void mma_f16(float* c,
                                        uint32_t a0, uint32_t a1, uint32_t a2, uint32_t a3,
                                        uint32_t b0, uint32_t b1) {
    asm volatile(
        "mma.sync.aligned.m16n8k16.row.col.f32.f16.f16.f32 "
        "{%0,%1,%2,%3}, {%4,%5,%6,%7}, {%8,%9}, {%0,%1,%2,%3};\n"
        : "+f"(c[0]), "+f"(c[1]), "+f"(c[2]), "+f"(c[3])
        : "r"(a0), "r"(a1), "r"(a2), "r"(a3), "r"(b0), "r"(b1));
}

__device__ __forceinline__ void ldsm_x4(uint32_t& r0, uint32_t& r1,
                                        uint32_t& r2, uint32_t& r3, uint32_t addr) {
    asm volatile("ldmatrix.sync.aligned.m8n8.x4.shared.b16 {%0,%1,%2,%3}, [%4];"
                 : "=r"(r0), "=r"(r1), "=r"(r2), "=r"(r3) : "r"(addr));
}

__device__ __forceinline__ uint32_t pack2(float lo, float hi) {
    __half2 h = __floats2half2_rn(lo, hi);
    return *reinterpret_cast<uint32_t*>(&h);
}

// ---------------------------------------------------------------------------
// Fused pre-pass: pure fp32 -> fp16 convert, natural order.
// ---------------------------------------------------------------------------
#define N4X (M_TOTAL * D_ / 4)     // 2097152
#define N4W (D_ * D_ / 4)          // 262144

__global__ __launch_bounds__(256)
void prep_all(const float* __restrict__ x,
              const float* __restrict__ Wq, const float* __restrict__ Wk,
              const float* __restrict__ Wv, const float* __restrict__ Wo)
{
    const int i = blockIdx.x * blockDim.x + threadIdx.x;
    const float* src;
    __half* dst;
    int j;
    if (i < N4X)                  { src = x;  dst = g_xh; j = i; }
    else {
        const int r = i - N4X;
        const int w = r >> 18;
        j = r & (N4W - 1);
        if      (w == 0) { src = Wq; dst = g_wq; }
        else if (w == 1) { src = Wk; dst = g_wk; }
        else if (w == 2) { src = Wv; dst = g_wv; }
        else             { src = Wo; dst = g_wo; }
    }
    const float4 v = ((const float4*)src)[j];
    const int flat = j << 2;
    *(__half2*)(dst + flat)     = __floats2half2_rn(v.x, v.y);
    *(__half2*)(dst + flat + 2) = __floats2half2_rn(v.z, v.w);
}

// ---------------------------------------------------------------------------
// fp16 GEMM (NT): CTA 128x128, 256 threads (8 warps of 32x64), BK=64,
// 2-buffer cp.async, 2 CTAs/SM. Stride 72 halves (ldmatrix conflict-free).
// ldmatrix.x4 fragments; 24 ldsm + 64 HMMA per warp per interval.
// ---------------------------------------------------------------------------
#define GBM 128
#define GBN 128
#define GBKH 64
#define GLDH 72
#define GBUFH ((GBM + GBN) * GLDH)               // 18432 halves / buffer
#define GEMM_SMEM (2 * GBUFH * 2)                // 73728 bytes
#define MT_STRIDE (16 * GLDH * 2)                // bytes per 16 rows

__global__ __launch_bounds__(256, 2)
void gemm_h(const __half* __restrict__ A,
            const __half* __restrict__ W0, const __half* __restrict__ W1,
            const __half* __restrict__ W2,
            const float* __restrict__ bb0, const float* __restrict__ bb1,
            const float* __restrict__ bb2,
            void* C0, void* C1, void* C2,
            int oproj)
{
    extern __shared__ __half smh[];
    const int z = blockIdx.z;
    const __half* Bw   = (z == 0) ? W0  : (z == 1) ? W1  : W2;
    const float*  bias = (z == 0) ? bb0 : (z == 1) ? bb1 : bb2;
    void*         C    = (z == 0) ? C0  : (z == 1) ? C1  : C2;
    const float scale  = (!oproj && z == 0) ? 0.125f : 1.0f;

    const int tid  = threadIdx.x;
    const int wid  = tid >> 5;
    const int lane = tid & 31;
    const int g    = lane >> 2;
    const int tig  = lane & 3;
    const int wm   = (wid & 3) * 32;     // 4 m-warps x 2 n-warps
    const int wn   = (wid >> 2) * 64;
    const int bm   = blockIdx.y * GBM;
    const int bn   = blockIdx.x * GBN;

    const __half* Abase = A  + (size_t)bm * D_;
    const __half* Bbase = Bw + (size_t)bn * D_;
    const uint32_t su   = smem_u32(smh);

    // ldmatrix per-lane address bases (byte offsets within a buffer)
    const int lrow8 = lane & 7;
    const int lgrp  = lane >> 3;    // 0..3
    // A x4: [m0-7,k0][m8-15,k0][m0-7,k+8][m8-15,k+8] -> a0,a1,a2,a3
    const uint32_t aoff =
        ((wm + (lgrp & 1) * 8 + lrow8) * GLDH + (lgrp >> 1) * 8) * 2;
    // B x4: [nt0,k0][nt0,k+8][nt1,k0][nt1,k+8] -> (b0,b1) of nt0, nt1
    const uint32_t boff =
        ((GBM + wn + (lgrp >> 1) * 8 + lrow8) * GLDH + (lgrp & 1) * 8) * 2;

#define G_ISSUE(slab, buf) do {                                            \
        const uint32_t s0 = su + (uint32_t)(buf) * (GBUFH * 2);            \
        const int k0 = (slab) * GBKH;                                      \
        _Pragma("unroll")                                                  \
        for (int j = 0; j < 4; j++) {                                      \
            const int i = tid + 256 * j;      /* A: 1024 16B chunks */     \
            const int row = i >> 3, ch = (i & 7) * 8;                      \
            cpa16(s0 + (row * GLDH + ch) * 2,                              \
                  Abase + (size_t)row * D_ + k0 + ch);                     \
        }                                                                  \
        _Pragma("unroll")                                                  \
        for (int j = 0; j < 4; j++) {                                      \
            const int i = tid + 256 * j;      /* B: 1024 16B chunks */     \
            const int row = i >> 3, ch = (i & 7) * 8;                      \
            cpa16(s0 + ((GBM + row) * GLDH + ch) * 2,                      \
                  Bbase + (size_t)row * D_ + k0 + ch);                     \
        }                                                                  \
        cpa_commit();                                                      \
    } while (0)

    float acc[2][8][4];
#pragma unroll
    for (int mt = 0; mt < 2; mt++)
#pragma unroll
        for (int nt = 0; nt < 8; nt++)
#pragma unroll
            for (int i = 0; i < 4; i++) acc[mt][nt][i] = 0.f;

    const int NT = D_ / GBKH;   // 16
    G_ISSUE(0, 0);
    G_ISSUE(1, 1);

    for (int t = 0; t < NT; t++) {
        if (t == NT - 1) cpa_wait0(); else cpa_wait1();
        __syncthreads();

        const uint32_t sbuf = su + (uint32_t)(t & 1) * (GBUFH * 2);
#pragma unroll
        for (int ks = 0; ks < 4; ks++) {
            uint32_t af[2][4];
#pragma unroll
            for (int mt = 0; mt < 2; mt++)
                ldsm_x4(af[mt][0], af[mt][1], af[mt][2], af[mt][3],
                        sbuf + aoff + mt * MT_STRIDE + ks * 32);
            uint32_t bfr[8][2];
#pragma unroll
            for (int p = 0; p < 4; p++)
                ldsm_x4(bfr[2 * p][0], bfr[2 * p][1],
                        bfr[2 * p + 1][0], bfr[2 * p + 1][1],
                        sbuf + boff + p * MT_STRIDE + ks * 32);
#pragma unroll
            for (int nt = 0; nt < 8; nt++)
#pragma unroll
                for (int mt = 0; mt < 2; mt++)
                    mma_f16(acc[mt][nt], af[mt][0], af[mt][1], af[mt][2], af[mt][3],
                            bfr[nt][0], bfr[nt][1]);
        }
        __syncthreads();                 // compute done before reissue
        if (t + 2 < NT) G_ISSUE(t + 2, t & 1);
    }
#undef G_ISSUE

    if (oproj) {
        float* Co = (float*)C;
#pragma unroll
        for (int mt = 0; mt < 2; mt++) {
            const int row0 = bm + wm + mt * 16 + g;
#pragma unroll
            for (int nt = 0; nt < 8; nt++) {
                const int col = bn + wn + nt * 8 + 2 * tig;
                const float c0 = bias[col], c1 = bias[col + 1];
                float2 v0 = make_float2(acc[mt][nt][0] + c0, acc[mt][nt][1] + c1);
                float2 v1 = make_float2(acc[mt][nt][2] + c0, acc[mt][nt][3] + c1);
                *(float2*)(Co + (size_t)row0 * D_ + col)       = v0;
                *(float2*)(Co + (size_t)(row0 + 8) * D_ + col) = v1;
            }
        }
    } else if (z < 2) {
        // q/k outputs: unit-permuted in head-dim (attention's LDS.64 frags)
        __half* Ch = (__half*)C;
#pragma unroll
        for (int mt = 0; mt < 2; mt++) {
            const int row0 = bm + wm + mt * 16 + g;
#pragma unroll
            for (int nt = 0; nt < 8; nt++) {
                const int n = bn + wn + nt * 8 + 2 * tig;
                const int dsti = bn + wn + (nt & ~1) * 8 + 4 * tig + 2 * (nt & 1);
                const float c0 = bias[n], c1 = bias[n + 1];
                *(__half2*)(Ch + (size_t)row0 * D_ + dsti) =
                    __floats2half2_rn((acc[mt][nt][0] + c0) * scale,
                                      (acc[mt][nt][1] + c1) * scale);
                *(__half2*)(Ch + (size_t)(row0 + 8) * D_ + dsti) =
                    __floats2half2_rn((acc[mt][nt][2] + c0) * scale,
                                      (acc[mt][nt][3] + c1) * scale);
            }
        }
    } else {
        // transposed Vt output with unit-permuted key positions
        __half* Vt = (__half*)C;
#pragma unroll
        for (int mt = 0; mt < 2; mt++) {
            const int row0 = bm + wm + mt * 16 + g;
#pragma unroll
            for (int nt = 0; nt < 8; nt++) {
                const int n  = bn + wn + nt * 8 + 2 * tig;
                const float c0 = bias[n], c1 = bias[n + 1];
#pragma unroll
                for (int e = 0; e < 4; e++) {
                    const int row = row0 + (e >> 1) * 8;
                    const int col = n + (e & 1);
                    const float val = acc[mt][nt][e] + ((e & 1) ? c1 : c0);
                    const int bIdx = row >> 10, s = row & 1023;
                    const int u    = (s >> 1) & 7;
                    const int sp   = (s & ~15) + 2 * (((u & 3) << 1) | (u >> 2)) + (s & 1);
                    const int head = col >> 6,  dd = col & 63;
                    Vt[(((size_t)(bIdx * H_ + head)) * HD_ + dd) * S_ + sp] =
                        __float2half_rn(val);
                }
            }
        }
    }
}

// ---------------------------------------------------------------------------
// Flash attention (round 14, unchanged): 4-stage cp.async K/V ring, single
// barrier per iteration, staging before compute. Q frags hoisted;
// Vt key-permuted; output ch unpermuted for the ldmatrix O-proj.
// ---------------------------------------------------------------------------
#define QLDH 80
#define KLDH 80
#define VLDH 80
#define OFF_K(s) (128 * QLDH + (s) * 64 * KLDH)
#define OFF_V(s) (128 * QLDH + 4 * 64 * KLDH + (s) * 64 * VLDH)
#define ATTN_SMEM ((128 * QLDH + 8 * 64 * KLDH) * 2)   // 102400 B

__global__ __launch_bounds__(128, 2)
void attn_h(const __half* __restrict__ Q, const __half* __restrict__ K,
            const __half* __restrict__ Vt, __half* __restrict__ O)
{
    extern __shared__ __half smh[];
    const uint32_t su = smem_u32(smh);

    const int q0   = blockIdx.x * 128;
    const int h    = blockIdx.y;
    const int b    = blockIdx.z;
    const int tid  = threadIdx.x;
    const int w    = tid >> 5;
    const int lane = tid & 31;
    const int g    = lane >> 2;
    const int tig  = lane & 3;

    const size_t base  = (size_t)b * S_ * D_ + (size_t)h * HD_;
    const size_t vbase = ((size_t)(b * H_ + h)) * HD_ * S_;

#define A_ISSUE(t) do {                                                    \
        const int sbuf = (t) & 3;                                          \
        const __half* Kb = K  + base + (size_t)((t) * 64) * D_;            \
        const __half* Vb = Vt + vbase + (t) * 64;                          \
        _Pragma("unroll")                                                  \
        for (int j = 0; j < 4; j++) {                                      \
            const int i = tid + 128 * j;                                   \
            const int row = i >> 3, ch = (i & 7) * 8;                      \
            cpa16(su + (OFF_K(sbuf) + row * KLDH + ch) * 2,                \
                  Kb + (size_t)row * D_ + ch);                             \
            cpa16(su + (OFF_V(sbuf) + row * VLDH + ch) * 2,                \
                  Vb + (size_t)row * S_ + ch);                             \
        }                                                                  \
        cpa_commit();                                                      \
    } while (0)

    {
        const __half* Qb = Q + base + (size_t)q0 * D_;
#pragma unroll
        for (int j = 0; j < 8; j++) {
            const int i = tid + 128 * j;
            const int row = i >> 3, ch = (i & 7) * 8;
            cpa16(su + (row * QLDH + ch) * 2, Qb + (size_t)row * D_ + ch);
        }
        const __half* Kb = K + base;
        const __half* Vb = Vt + vbase;
#pragma unroll
        for (int j = 0; j < 4; j++) {
            const int i = tid + 128 * j;
            const int row = i >> 3, ch = (i & 7) * 8;
            cpa16(su + (OFF_K(0) + row * KLDH + ch) * 2, Kb + (size_t)row * D_ + ch);
            cpa16(su + (OFF_V(0) + row * VLDH + ch) * 2, Vb + (size_t)row * S_ + ch);
        }
        cpa_commit();
        A_ISSUE(1);
        A_ISSUE(2);
    }

    float mrow[2][2], lrow[2][2];
#pragma unroll
    for (int mt = 0; mt < 2; mt++) {
        mrow[mt][0] = -1e30f; mrow[mt][1] = -1e30f;
        lrow[mt][0] = 0.f;    lrow[mt][1] = 0.f;
    }
    float o[2][8][4];
#pragma unroll
    for (int mt = 0; mt < 2; mt++)
#pragma unroll
        for (int nt = 0; nt < 8; nt++)
#pragma unroll
            for (int i = 0; i < 4; i++) o[mt][nt][i] = 0.f;

    uint2 qlo[2][4], qhi[2][4];

    const int NTILE = S_ / 64;   // 16
    for (int t = 0; t < NTILE; t++) {
        if (t <= NTILE - 3)      cpa_wait2();
        else if (t == NTILE - 2) cpa_wait1();
        else                     cpa_wait0();
        __syncthreads();

        if (t + 3 < NTILE) A_ISSUE(t + 3);

        if (t == 0) {
#pragma unroll
            for (int ks = 0; ks < 4; ks++)
#pragma unroll
                for (int mt = 0; mt < 2; mt++) {
                    const int r0 = (w * 32 + mt * 16 + g) * QLDH + ks * 16 + 4 * tig;
                    qlo[mt][ks] = *(const uint2*)&smh[r0];
                    qhi[mt][ks] = *(const uint2*)&smh[r0 + 8 * QLDH];
                }
        }

        const __half* sK = smh + OFF_K(t & 3);
        const __half* sV = smh + OFF_V(t & 3);

        float s[2][8][4];
#pragma unroll
        for (int mt = 0; mt < 2; mt++)
#pragma unroll
            for (int nt = 0; nt < 8; nt++)
#pragma unroll
                for (int i = 0; i < 4; i++) s[mt][nt][i] = 0.f;

#pragma unroll
        for (int ks = 0; ks < 4; ks++) {
#pragma unroll
            for (int nt = 0; nt < 8; nt++) {
                const uint2 bb = *(const uint2*)&sK[(nt * 8 + g) * KLDH
                                                    + ks * 16 + 4 * tig];
                mma_f16(s[0][nt], qlo[0][ks].x, qhi[0][ks].x, qlo[0][ks].y,
                        qhi[0][ks].y, bb.x, bb.y);
                mma_f16(s[1][nt], qlo[1][ks].x, qhi[1][ks].x, qlo[1][ks].y,
                        qhi[1][ks].y, bb.x, bb.y);
            }
        }

#pragma unroll
        for (int mt = 0; mt < 2; mt++) {
            float mx0 = -1e30f, mx1 = -1e30f;
#pragma unroll
            for (int nt = 0; nt < 8; nt++) {
                mx0 = fmaxf(mx0, fmaxf(s[mt][nt][0], s[mt][nt][1]));
                mx1 = fmaxf(mx1, fmaxf(s[mt][nt][2], s[mt][nt][3]));
            }
            mx0 = fmaxf(mx0, __shfl_xor_sync(0xffffffffu, mx0, 1));
            mx0 = fmaxf(mx0, __shfl_xor_sync(0xffffffffu, mx0, 2));
            mx1 = fmaxf(mx1, __shfl_xor_sync(0xffffffffu, mx1, 1));
            mx1 = fmaxf(mx1, __shfl_xor_sync(0xffffffffu, mx1, 2));

            const float nm0 = fmaxf(mrow[mt][0], mx0);
            const float nm1 = fmaxf(mrow[mt][1], mx1);
            const float al0 = __expf(mrow[mt][0] - nm0);
            const float al1 = __expf(mrow[mt][1] - nm1);
            mrow[mt][0] = nm0; mrow[mt][1] = nm1;

            float ps0 = 0.f, ps1 = 0.f;
#pragma unroll
            for (int nt = 0; nt < 8; nt++) {
                s[mt][nt][0] = __expf(s[mt][nt][0] - nm0);
                s[mt][nt][1] = __expf(s[mt][nt][1] - nm0);
                s[mt][nt][2] = __expf(s[mt][nt][2] - nm1);
                s[mt][nt][3] = __expf(s[mt][nt][3] - nm1);
                ps0 += s[mt][nt][0] + s[mt][nt][1];
                ps1 += s[mt][nt][2] + s[mt][nt][3];
            }
            ps0 += __shfl_xor_sync(0xffffffffu, ps0, 1);
            ps0 += __shfl_xor_sync(0xffffffffu, ps0, 2);
            ps1 += __shfl_xor_sync(0xffffffffu, ps1, 1);
            ps1 += __shfl_xor_sync(0xffffffffu, ps1, 2);
            lrow[mt][0] = lrow[mt][0] * al0 + ps0;
            lrow[mt][1] = lrow[mt][1] * al1 + ps1;

#pragma unroll
            for (int nt = 0; nt < 8; nt++) {
                o[mt][nt][0] *= al0; o[mt][nt][1] *= al0;
                o[mt][nt][2] *= al1; o[mt][nt][3] *= al1;
            }
        }

#pragma unroll
        for (int ks = 0; ks < 4; ks++) {
            uint32_t pa[2][4];
#pragma unroll
            for (int mt = 0; mt < 2; mt++) {
                pa[mt][0] = pack2(s[mt][2 * ks][0],     s[mt][2 * ks][1]);
                pa[mt][1] = pack2(s[mt][2 * ks][2],     s[mt][2 * ks][3]);
                pa[mt][2] = pack2(s[mt][2 * ks + 1][0], s[mt][2 * ks + 1][1]);
                pa[mt][3] = pack2(s[mt][2 * ks + 1][2], s[mt][2 * ks + 1][3]);
            }
#pragma unroll
            for (int nt = 0; nt < 8; nt++) {
                const uint2 bb = *(const uint2*)&sV[(nt * 8 + g) * VLDH
                                                    + ks * 16 + 4 * tig];
                mma_f16(o[0][nt], pa[0][0], pa[0][1], pa[0][2], pa[0][3], bb.x, bb.y);
                mma_f16(o[1][nt], pa[1][0], pa[1][1], pa[1][2], pa[1][3], bb.x, bb.y);
            }
        }
    }
#undef A_ISSUE

    // ---- write out fp16, natural (unpermuted) head-dim for ldmatrix O-proj
#pragma unroll
    for (int mt = 0; mt < 2; mt++) {
        const float inv0 = 1.f / lrow[mt][0];
        const float inv1 = 1.f / lrow[mt][1];
        const int row = q0 + w * 32 + mt * 16 + g;
#pragma unroll
        for (int nt = 0; nt < 8; nt++) {
            const int dsti = h * HD_ + nt * 8 + 2 * tig;
            *(__half2*)(O + (size_t)(b * S_ + row) * D_ + dsti) =
                __floats2half2_rn(o[mt][nt][0] * inv0, o[mt][nt][1] * inv0);
            *(__half2*)(O + (size_t)(b * S_ + row + 8) * D_ + dsti) =
                __floats2half2_rn(o[mt][nt][2] * inv1, o[mt][nt][3] * inv1);
        }
    }
}

// ---------------------------------------------------------------------------
// Launch
// ---------------------------------------------------------------------------
extern "C" void kernel_launch(void* const* d_in, const int* in_sizes, int n_in,
                              void* d_out, int out_size)
{
    const float* x  = (const float*)d_in[0];
    const float* Wq = (const float*)d_in[1];
    const float* Wk = (const float*)d_in[2];
    const float* Wv = (const float*)d_in[3];
    const float* bq = (const float*)d_in[4];
    const float* bk = (const float*)d_in[5];
    const float* bv = (const float*)d_in[6];
    const float* Wo = (const float*)d_in[7];
    const float* bo = (const float*)d_in[8];
    float* out = (float*)d_out;

    __half *xh, *qh, *kh, *vt, *ch, *wqh, *wkh, *wvh, *woh;
    cudaGetSymbolAddress((void**)&xh,  g_xh);
    cudaGetSymbolAddress((void**)&qh,  g_qh);
    cudaGetSymbolAddress((void**)&kh,  g_kh);
    cudaGetSymbolAddress((void**)&vt,  g_vt);
    cudaGetSymbolAddress((void**)&ch,  g_ch);
    cudaGetSymbolAddress((void**)&wqh, g_wq);
    cudaGetSymbolAddress((void**)&wkh, g_wk);
    cudaGetSymbolAddress((void**)&wvh, g_wv);
    cudaGetSymbolAddress((void**)&woh, g_wo);

    cudaFuncSetAttribute(gemm_h,
                         cudaFuncAttributeMaxDynamicSharedMemorySize, GEMM_SMEM);
    cudaFuncSetAttribute(attn_h,
                         cudaFuncAttributeMaxDynamicSharedMemorySize, ATTN_SMEM);

    const int n4all = N4X + 4 * N4W;
    prep_all<<<n4all / 256, 256>>>(x, Wq, Wk, Wv, Wo);

    // fused QKV: z=0 -> q (scale 0.125), z=1 -> k, z=2 -> Vt (key-permuted)
    gemm_h<<<dim3(D_ / GBN, M_TOTAL / GBM, 3), 256, GEMM_SMEM>>>(
        xh, wqh, wkh, wvh, bq, bk, bv, qh, kh, vt, 0);

    attn_h<<<dim3(S_ / 128, H_, B_), 128, ATTN_SMEM>>>(qh, kh, vt, ch);

    // output projection: fp32 plain out
    gemm_h<<<dim3(D_ / GBN, M_TOTAL / GBM, 1), 256, GEMM_SMEM>>>(
        ch, woh, woh, woh, bo, bo, bo, out, out, out, 1);
}